// round 6
// baseline (speedup 1.0000x reference)
#include <cuda_runtime.h>
#include <math.h>

#define HEADS 16
#define HD    32
#define CDIM  512
#define NREF  100
#define LTOK  12544
#define TTOK  25088
#define RH    12544
#define RW    100
#define PLANE ((size_t)RH*RW)
#define EPSV  1e-5f
#define SCALEV 0.17677669529663687f

// ---------- scratch ----------
static __device__ float g_xw [(size_t)TTOK*CDIM];
static __device__ float g_qkv[(size_t)TTOK*3*CDIM];
static __device__ float g_refq[2*HEADS*NREF*HD];
static __device__ float g_refv[2*HEADS*NREF*HD];
static __device__ float g_ra [(size_t)32*PLANE];
static __device__ float g_u  [(size_t)32*PLANE];
static __device__ float g_ao [(size_t)TTOK*CDIM];
static __device__ float g_proj[(size_t)TTOK*CDIM];
static __device__ float g_x2 [(size_t)TTOK*CDIM];
static __device__ float g_ln2[(size_t)TTOK*CDIM];
static __device__ float g_fc1[(size_t)TTOK*4*CDIM];
static __device__ double g_ss[32], g_sq[32];

__device__ __forceinline__ float gelu_f(float x){
    return 0.5f*x*(1.f+erff(x*0.70710678118654752f));
}

// block-wide LN stats for a 512-wide row held as (v0,v1) per thread (256 threads)
__device__ __forceinline__ void ln_stats(float v0, float v1, float& mu, float& rs){
    __shared__ float r1[8], r2[8];
    __shared__ float smu, srs;
    float s=v0+v1, q=v0*v0+v1*v1;
    #pragma unroll
    for(int o=16;o;o>>=1){ s+=__shfl_xor_sync(~0u,s,o); q+=__shfl_xor_sync(~0u,q,o); }
    int tid=threadIdx.x;
    if((tid&31)==0){ r1[tid>>5]=s; r2[tid>>5]=q; }
    __syncthreads();
    if(tid==0){
        float S=0.f,Q=0.f;
        #pragma unroll
        for(int i=0;i<8;i++){S+=r1[i];Q+=r2[i];}
        float m=S*(1.f/512.f);
        smu=m; srs=rsqrtf(Q*(1.f/512.f)-m*m+EPSV);
    }
    __syncthreads();
    mu=smu; rs=srs;
}

// ---------- LN1 + shift(-3,-3) + window partition -> g_xw ----------
__global__ void __launch_bounds__(256) ln1_shift(const float* __restrict__ x,
    const float* __restrict__ w, const float* __restrict__ b)
{
    int t=blockIdx.x, tid=threadIdx.x;
    int win=t/49, n=t-49*win;
    int bb=win>>8, wi=win&255;
    int r=n/7, c=n-7*r;
    int hs=(wi>>4)*7 + r + 3; if(hs>=112) hs-=112;
    int ws=(wi&15)*7 + c + 3; if(ws>=112) ws-=112;
    const float* xr = x + ((size_t)bb*LTOK + hs*112 + ws)*CDIM;
    float v0=xr[tid], v1=xr[tid+256];
    float mu,rs; ln_stats(v0,v1,mu,rs);
    float* o = g_xw + (size_t)t*CDIM;
    o[tid]      =(v0-mu)*rs*w[tid]      +b[tid];
    o[tid+256]  =(v1-mu)*rs*w[tid+256]  +b[tid+256];
}

// ---------- generic NT SGEMM: C[M,Nc]=A[M,K]@W[Nc,K]^T (+epilogue) ----------
// EPI 0: +bias   1: gelu(+bias)   2: +bias+add
template<int EPI>
__global__ void __launch_bounds__(256) sgemm_nt(const float* __restrict__ A,
    const float* __restrict__ W, const float* __restrict__ bias,
    const float* __restrict__ add, float* __restrict__ C, int Nc, int K)
{
    __shared__ __align__(16) float As[16][128];
    __shared__ __align__(16) float Bs[16][128];
    int tid=threadIdx.x;
    int bm=blockIdx.y*128, bn=blockIdx.x*128;
    int lrow=tid>>1, lcol=(tid&1)*8;
    const float* Ap=A+(size_t)(bm+lrow)*K+lcol;
    const float* Wp=W+(size_t)(bn+lrow)*K+lcol;
    int ty=tid>>4, tx=tid&15;
    float acc[8][8];
    #pragma unroll
    for(int i=0;i<8;i++){
        #pragma unroll
        for(int j=0;j<8;j++) acc[i][j]=0.f;
    }
    for(int k0=0;k0<K;k0+=16){
        float4 a0=*(const float4*)(Ap+k0), a1=*(const float4*)(Ap+k0+4);
        float4 w0=*(const float4*)(Wp+k0), w1=*(const float4*)(Wp+k0+4);
        As[lcol+0][lrow]=a0.x; As[lcol+1][lrow]=a0.y; As[lcol+2][lrow]=a0.z; As[lcol+3][lrow]=a0.w;
        As[lcol+4][lrow]=a1.x; As[lcol+5][lrow]=a1.y; As[lcol+6][lrow]=a1.z; As[lcol+7][lrow]=a1.w;
        Bs[lcol+0][lrow]=w0.x; Bs[lcol+1][lrow]=w0.y; Bs[lcol+2][lrow]=w0.z; Bs[lcol+3][lrow]=w0.w;
        Bs[lcol+4][lrow]=w1.x; Bs[lcol+5][lrow]=w1.y; Bs[lcol+6][lrow]=w1.z; Bs[lcol+7][lrow]=w1.w;
        __syncthreads();
        #pragma unroll
        for(int k=0;k<16;k++){
            float4 x0=*(const float4*)&As[k][ty*4];
            float4 x1=*(const float4*)&As[k][64+ty*4];
            float4 y0=*(const float4*)&Bs[k][tx*4];
            float4 y1=*(const float4*)&Bs[k][64+tx*4];
            float a[8]={x0.x,x0.y,x0.z,x0.w,x1.x,x1.y,x1.z,x1.w};
            float bb[8]={y0.x,y0.y,y0.z,y0.w,y1.x,y1.y,y1.z,y1.w};
            #pragma unroll
            for(int i=0;i<8;i++){
                #pragma unroll
                for(int j=0;j<8;j++) acc[i][j]+=a[i]*bb[j];
            }
        }
        __syncthreads();
    }
    #pragma unroll
    for(int i=0;i<8;i++){
        int row=bm+(i>>2)*64+ty*4+(i&3);
        #pragma unroll
        for(int jb=0;jb<2;jb++){
            int col=bn+jb*64+tx*4;
            float4 bv=*(const float4*)(bias+col);
            float4 v;
            v.x=acc[i][jb*4+0]+bv.x; v.y=acc[i][jb*4+1]+bv.y;
            v.z=acc[i][jb*4+2]+bv.z; v.w=acc[i][jb*4+3]+bv.w;
            if(EPI==1){ v.x=gelu_f(v.x); v.y=gelu_f(v.y); v.z=gelu_f(v.z); v.w=gelu_f(v.w); }
            if(EPI==2){
                float4 av=*(const float4*)(add+(size_t)row*Nc+col);
                v.x+=av.x; v.y+=av.y; v.z+=av.z; v.w+=av.w;
            }
            *(float4*)(C+(size_t)row*Nc+col)=v;
        }
    }
}

// ---------- ref tokens: (x_ref @ ref_qk_w^T + b), reparam -> g_refq/g_refv ----------
__global__ void __launch_bounds__(256) refqk(const float* __restrict__ xr,
    const float* __restrict__ Wt, const float* __restrict__ bias,
    const float* __restrict__ dmu, const float* __restrict__ dls)
{
    __shared__ __align__(16) float xs[512];
    int row=blockIdx.x, tid=threadIdx.x;
    int rb=row/100, r=row-100*rb;
    const float* src=xr+(size_t)row*512;
    xs[tid]=src[tid]; xs[tid+256]=src[tid+256];
    __syncthreads();
    const float4* x4=(const float4*)xs;
    for(int rep=0;rep<4;rep++){
        int col=tid+rep*256;
        const float4* w4=(const float4*)(Wt+(size_t)col*512);
        float acc=bias[col];
        #pragma unroll 8
        for(int k=0;k<128;k++){
            float4 a=x4[k], b=w4[k];
            acc+=a.x*b.x+a.y*b.y+a.z*b.z+a.w*b.w;
        }
        if(col<512){
            int h=col>>5, d=col&31;
            g_refq[(((size_t)rb*16+h)*100+r)*32+d]=dmu[col]+expf(dls[col])*acc;
        }else{
            int cc=col-512, h=cc>>5, d=cc&31;
            g_refv[(((size_t)rb*16+h)*100+r)*32+d]=acc;
        }
    }
}

// ---------- ra = q @ ref_q^T per (window, head) -> conv layout ----------
__global__ void __launch_bounds__(256) ra_kernel()
{
    __shared__ float qs[1568];
    __shared__ float rs[3300];   // 100 rows, stride 33
    int bx=blockIdx.x, tid=threadIdx.x;
    int win=bx>>4, h=bx&15, rb=win>>8, winb=win&255;
    for(int i=tid;i<1568;i+=256){
        int n=i>>5, d=i&31;
        qs[i]=g_qkv[(size_t)(win*49+n)*1536 + h*32 + d];
    }
    const float* rq = g_refq + (size_t)(rb*16+h)*3200;
    for(int i=tid;i<3200;i+=256){
        int r=i>>5, d=i&31;
        rs[r*33+d]=rq[i];
    }
    __syncthreads();
    float* out = g_ra + ((size_t)(rb*16+h)*RH + winb*49)*100;
    for(int idx=tid;idx<4900;idx+=256){
        int n=idx/100, r=idx-100*n;
        const float* q=qs+n*32; const float* rr=rs+r*33;
        float acc=0.f;
        #pragma unroll
        for(int k=0;k<32;k++) acc+=q[k]*rr[k];
        out[idx]=acc;
    }
}

// ---------- conv diffusion ----------
__global__ void zero_stats(){
    if(threadIdx.x<32){ g_ss[threadIdx.x]=0.0; g_sq[threadIdx.x]=0.0; }
}

__global__ void __launch_bounds__(256) conv3x3(const float* __restrict__ cw,
    const float* __restrict__ cb)
{
    __shared__ float s_in[16][4][102];
    __shared__ __align__(16) float s_w[2304];   // [(ci*9+tap)*16+co]
    __shared__ float red_s[8][16], red_q[8][16];
    int tid=threadIdx.y*128+threadIdx.x;
    int h0=blockIdx.x*2, nb=blockIdx.y;
    for(int i=tid;i<2304;i+=256){
        int ci=i/144, t2=i-144*ci, tap=t2>>4, co=t2&15;
        s_w[i]=cw[(co*16+ci)*9+tap];
    }
    for(int i=tid;i<6528;i+=256){
        int ci=i/408, t2=i-408*ci, rr=t2/102, cc=t2-102*rr;
        int gr=h0-1+rr, gc=cc-1;
        float v=0.f;
        if(gr>=0 && gr<RH && gc>=0 && gc<100)
            v=g_ra[((size_t)(nb*16+ci)*RH+gr)*100+gc];
        s_in[ci][rr][cc]=v;
    }
    __syncthreads();
    int w=threadIdx.x, y=threadIdx.y;
    bool act=(w<100);
    float acc[16];
    #pragma unroll
    for(int co=0;co<16;co++) acc[co]=cb[co];
    if(act){
        #pragma unroll 4
        for(int ci=0;ci<16;ci++){
            #pragma unroll
            for(int dr=0;dr<3;dr++){
                #pragma unroll
                for(int dc=0;dc<3;dc++){
                    float v=s_in[ci][y+dr][w+dc];
                    const float4* wp=(const float4*)&s_w[(ci*9+dr*3+dc)*16];
                    #pragma unroll
                    for(int q=0;q<4;q++){
                        float4 ww=wp[q];
                        acc[q*4+0]+=ww.x*v; acc[q*4+1]+=ww.y*v;
                        acc[q*4+2]+=ww.z*v; acc[q*4+3]+=ww.w*v;
                    }
                }
            }
        }
        int hh=h0+y;
        #pragma unroll
        for(int co=0;co<16;co++)
            g_u[((size_t)(nb*16+co)*RH+hh)*100+w]=acc[co];
    }
    int wp2=tid>>5, lane=tid&31;
    #pragma unroll
    for(int co=0;co<16;co++){
        float s=act?acc[co]:0.f;
        float q=s*s;
        #pragma unroll
        for(int o=16;o;o>>=1){ s+=__shfl_xor_sync(~0u,s,o); q+=__shfl_xor_sync(~0u,q,o); }
        if(lane==0){ red_s[wp2][co]=s; red_q[wp2][co]=q; }
    }
    __syncthreads();
    if(tid<16){
        float S=0.f,Q=0.f;
        #pragma unroll
        for(int i=0;i<8;i++){ S+=red_s[i][tid]; Q+=red_q[i][tid]; }
        atomicAdd(&g_ss[nb*16+tid],(double)S);
        atomicAdd(&g_sq[nb*16+tid],(double)Q);
    }
}

__global__ void __launch_bounds__(256) norm_gelu()
{
    int p=blockIdx.y;
    size_t base=(size_t)p*PLANE + (size_t)blockIdx.x*256 + threadIdx.x;
    double cnt=1254400.0;
    double mu=g_ss[p]/cnt;
    double var=g_sq[p]/cnt - mu*mu;
    float rs=(float)rsqrt(var+1e-5);
    float m=(float)mu;
    float u=g_u[base];
    g_ra[base]+=gelu_f((u-m)*rs);
}

// ---------- fused attention per (window, head) ----------
__global__ void __launch_bounds__(256) attn_kernel(const float* __restrict__ mask,
    const float* __restrict__ rpb)
{
    __shared__ float A[4900];   // ra (49x100) -> scores (49 rows, stride 50)
    __shared__ float B[3200];   // refv (stride 32) -> k (stride 33)
    __shared__ float Q[1568];   // q_new (stride 32)
    __shared__ float V[1617];   // v (stride 33)
    int bx=blockIdx.x, tid=threadIdx.x;
    int win=bx>>4, h=bx&15, rb=win>>8, winb=win&255;
    int plane=rb*16+h;
    const float* raP=g_ra + ((size_t)plane*RH + winb*49)*100;
    for(int i=tid;i<4900;i+=256) A[i]=raP[i];
    const float* rvP=g_refv + (size_t)plane*3200;
    for(int i=tid;i<3200;i+=256) B[i]=rvP[i];
    for(int i=tid;i<1568;i+=256){
        int n=i>>5, d=i&31;
        V[n*33+d]=g_qkv[(size_t)(win*49+n)*1536 + 1024 + h*32 + d];
    }
    __syncthreads();
    int wp=tid>>5, lane=tid&31;
    // softmax over 100 per row
    for(int n=wp;n<49;n+=8){
        float* row=A+n*100;
        float e0=row[lane], e1=row[lane+32], e2=row[lane+64];
        float e3=(lane<4)?row[lane+96]:-1e30f;
        float m=fmaxf(fmaxf(e0,e1),fmaxf(e2,e3));
        #pragma unroll
        for(int o=16;o;o>>=1) m=fmaxf(m,__shfl_xor_sync(~0u,m,o));
        e0=__expf(e0-m); e1=__expf(e1-m); e2=__expf(e2-m);
        e3=(lane<4)?__expf(e3-m):0.f;
        float s=e0+e1+e2+e3;
        #pragma unroll
        for(int o=16;o;o>>=1) s+=__shfl_xor_sync(~0u,s,o);
        float inv=1.f/s;
        row[lane]=e0*inv; row[lane+32]=e1*inv; row[lane+64]=e2*inv;
        if(lane<4) row[lane+96]=e3*inv;
    }
    __syncthreads();
    // q_new = ra @ refv * SCALE
    for(int idx=tid;idx<1568;idx+=256){
        int n=idx>>5, d=idx&31;
        float acc=0.f; const float* ar=A+n*100;
        #pragma unroll 4
        for(int r=0;r<100;r++) acc+=ar[r]*B[r*32+d];
        Q[idx]=acc*SCALEV;
    }
    __syncthreads();
    // load k into B (stride 33)
    for(int i=tid;i<1568;i+=256){
        int n=i>>5, d=i&31;
        B[n*33+d]=g_qkv[(size_t)(win*49+n)*1536 + 512 + h*32 + d];
    }
    __syncthreads();
    // scores = q_new @ k^T + rpb + mask  (into A, stride 50)
    const float* mrow=mask + (size_t)winb*2401;
    for(int idx=tid;idx<2401;idx+=256){
        int n=idx/49, m2=idx-49*n;
        float acc=0.f; const float* qr=Q+n*32; const float* kr=B+m2*33;
        #pragma unroll
        for(int k=0;k<32;k++) acc+=qr[k]*kr[k];
        int rpi=(n/7 - m2/7 + 6)*13 + (n%7 - m2%7 + 6);
        acc += rpb[rpi*16+h] + mrow[idx];
        A[n*50+m2]=acc;
    }
    __syncthreads();
    // softmax over 49 per row
    for(int n=wp;n<49;n+=8){
        float* row=A+n*50;
        float a0=row[lane];
        float a1=(lane<17)?row[lane+32]:-1e30f;
        float m=fmaxf(a0,a1);
        #pragma unroll
        for(int o=16;o;o>>=1) m=fmaxf(m,__shfl_xor_sync(~0u,m,o));
        a0=__expf(a0-m);
        a1=(lane<17)?__expf(a1-m):0.f;
        float s=a0+a1;
        #pragma unroll
        for(int o=16;o;o>>=1) s+=__shfl_xor_sync(~0u,s,o);
        float inv=1.f/s;
        row[lane]=a0*inv; if(lane<17) row[lane+32]=a1*inv;
    }
    __syncthreads();
    // out = attn @ v -> (token, h*32+d) layout
    for(int idx=tid;idx<1568;idx+=256){
        int n=idx>>5, d=idx&31;
        float acc=0.f; const float* sr=A+n*50;
        #pragma unroll 7
        for(int m2=0;m2<49;m2++) acc+=sr[m2]*V[m2*33+d];
        g_ao[(size_t)(win*49+n)*512 + h*32 + d]=acc;
    }
}

// ---------- window reverse + roll(+3,+3) + residual + LN2 ----------
__global__ void __launch_bounds__(256) rev_ln2(const float* __restrict__ x,
    const float* __restrict__ w, const float* __restrict__ b)
{
    int t=blockIdx.x, tid=threadIdx.x;
    int bb=t/LTOK, rem=t-bb*LTOK;
    int hh=rem/112, ww=rem-112*hh;
    int hs=hh+109; if(hs>=112) hs-=112;
    int ws=ww+109; if(ws>=112) ws-=112;
    int win=bb*256 + (hs/7)*16 + (ws/7);
    int n=(hs%7)*7 + (ws%7);
    const float* pr=g_proj + (size_t)(win*49+n)*512;
    const float* xr=x + (size_t)t*512;
    float v0=xr[tid]+pr[tid], v1=xr[tid+256]+pr[tid+256];
    float mu,rs; ln_stats(v0,v1,mu,rs);
    float* o2=g_x2 + (size_t)t*512;
    float* ol=g_ln2 + (size_t)t*512;
    o2[tid]=v0; o2[tid+256]=v1;
    ol[tid]    =(v0-mu)*rs*w[tid]    +b[tid];
    ol[tid+256]=(v1-mu)*rs*w[tid+256]+b[tid+256];
}

// ---------- launch ----------
extern "C" void kernel_launch(void* const* d_in, const int* in_sizes, int n_in,
                              void* d_out, int out_size)
{
    const float* x    =(const float*)d_in[0];
    const float* x_ref=(const float*)d_in[1];
    const float* mask =(const float*)d_in[2];
    const float* n1w  =(const float*)d_in[3];
    const float* n1b  =(const float*)d_in[4];
    const float* qkvw =(const float*)d_in[5];
    const float* qkvb =(const float*)d_in[6];
    const float* dmu  =(const float*)d_in[7];
    const float* dls  =(const float*)d_in[8];
    const float* rpb  =(const float*)d_in[9];
    const float* rqw  =(const float*)d_in[10];
    const float* rqb  =(const float*)d_in[11];
    const float* cw   =(const float*)d_in[12];
    const float* cb   =(const float*)d_in[13];
    const float* pw   =(const float*)d_in[14];
    const float* pb   =(const float*)d_in[15];
    const float* n2w  =(const float*)d_in[16];
    const float* n2b  =(const float*)d_in[17];
    const float* f1w  =(const float*)d_in[18];
    const float* f1b  =(const float*)d_in[19];
    const float* f2w  =(const float*)d_in[20];
    const float* f2b  =(const float*)d_in[21];
    float* out=(float*)d_out;
    (void)in_sizes; (void)n_in; (void)out_size;

    float *p_xw, *p_qkv, *p_ao, *p_proj, *p_ln2, *p_fc1, *p_x2;
    cudaGetSymbolAddress((void**)&p_xw,  g_xw);
    cudaGetSymbolAddress((void**)&p_qkv, g_qkv);
    cudaGetSymbolAddress((void**)&p_ao,  g_ao);
    cudaGetSymbolAddress((void**)&p_proj,g_proj);
    cudaGetSymbolAddress((void**)&p_ln2, g_ln2);
    cudaGetSymbolAddress((void**)&p_fc1, g_fc1);
    cudaGetSymbolAddress((void**)&p_x2,  g_x2);

    ln1_shift<<<TTOK,256>>>(x, n1w, n1b);
    sgemm_nt<0><<<dim3(12,196),256>>>(p_xw, qkvw, qkvb, nullptr, p_qkv, 1536, 512);
    refqk<<<200,256>>>(x_ref, rqw, rqb, dmu, dls);
    ra_kernel<<<8192,256>>>();
    for(int it=0; it<3; it++){
        zero_stats<<<1,32>>>();
        conv3x3<<<dim3(6272,2),dim3(128,2)>>>(cw, cb);
        norm_gelu<<<dim3(4900,32),256>>>();
    }
    attn_kernel<<<8192,256>>>(mask, rpb);
    sgemm_nt<0><<<dim3(4,196),256>>>(p_ao, pw, pb, nullptr, p_proj, 512, 512);
    rev_ln2<<<TTOK,256>>>(x, n2w, n2b);
    sgemm_nt<1><<<dim3(16,196),256>>>(p_ln2, f1w, f1b, nullptr, p_fc1, 2048, 512);
    sgemm_nt<2><<<dim3(4,196),256>>>(p_fc1, f2w, f2b, p_x2, out, 512, 2048);
}

// round 8
// speedup vs baseline: 1.1877x; 1.1877x over previous
#include <cuda_runtime.h>
#include <math.h>

#define HEADS 16
#define HD    32
#define CDIM  512
#define NREF  100
#define LTOK  12544
#define TTOK  25088
#define RH    12544
#define RW    100
#define PLANE ((size_t)RH*RW)
#define EPSV  1e-5f
#define SCALEV 0.17677669529663687f

// ---------- scratch ----------
static __device__ float g_xw [(size_t)TTOK*CDIM];
static __device__ float g_qkv[(size_t)TTOK*3*CDIM];
static __device__ float g_refq[2*HEADS*NREF*HD];
static __device__ float g_refv[2*HEADS*NREF*HD];
static __device__ float g_ra [(size_t)32*PLANE];
static __device__ float g_u  [(size_t)32*PLANE];
static __device__ float g_ao [(size_t)TTOK*CDIM];
static __device__ float g_proj[(size_t)TTOK*CDIM];
static __device__ float g_x2 [(size_t)TTOK*CDIM];
static __device__ float g_ln2[(size_t)TTOK*CDIM];
static __device__ float g_fc1[(size_t)TTOK*4*CDIM];
static __device__ double g_ss[32], g_sq[32];

__device__ __forceinline__ float gelu_f(float x){
    return 0.5f*x*(1.f+erff(x*0.70710678118654752f));
}

__device__ __forceinline__ unsigned f2tf(float f){
    unsigned u; asm("cvt.rna.tf32.f32 %0, %1;" : "=r"(u) : "f"(f)); return u;
}

// block-wide LN stats for a 512-wide row held as (v0,v1) per thread (256 threads)
__device__ __forceinline__ void ln_stats(float v0, float v1, float& mu, float& rs){
    __shared__ float r1[8], r2[8];
    __shared__ float smu, srs;
    float s=v0+v1, q=v0*v0+v1*v1;
    #pragma unroll
    for(int o=16;o;o>>=1){ s+=__shfl_xor_sync(~0u,s,o); q+=__shfl_xor_sync(~0u,q,o); }
    int tid=threadIdx.x;
    if((tid&31)==0){ r1[tid>>5]=s; r2[tid>>5]=q; }
    __syncthreads();
    if(tid==0){
        float S=0.f,Q=0.f;
        #pragma unroll
        for(int i=0;i<8;i++){S+=r1[i];Q+=r2[i];}
        float m=S*(1.f/512.f);
        smu=m; srs=rsqrtf(Q*(1.f/512.f)-m*m+EPSV);
    }
    __syncthreads();
    mu=smu; rs=srs;
}

// ---------- LN1 + shift(-3,-3) + window partition -> g_xw ----------
__global__ void __launch_bounds__(256) ln1_shift(const float* __restrict__ x,
    const float* __restrict__ w, const float* __restrict__ b)
{
    int t=blockIdx.x, tid=threadIdx.x;
    int win=t/49, n=t-49*win;
    int bb=win>>8, wi=win&255;
    int r=n/7, c=n-7*r;
    int hs=(wi>>4)*7 + r + 3; if(hs>=112) hs-=112;
    int ws=(wi&15)*7 + c + 3; if(ws>=112) ws-=112;
    const float* xr = x + ((size_t)bb*LTOK + hs*112 + ws)*CDIM;
    float v0=xr[tid], v1=xr[tid+256];
    float mu,rs; ln_stats(v0,v1,mu,rs);
    float* o = g_xw + (size_t)t*CDIM;
    o[tid]      =(v0-mu)*rs*w[tid]      +b[tid];
    o[tid+256]  =(v1-mu)*rs*w[tid+256]  +b[tid+256];
}

// ---------- TF32 tensor-core NT GEMM: C[M,Nc]=A[M,K]@W[Nc,K]^T (+epilogue) ----------
// 128x128x16 tile, 8 warps (4m x 2n), warp = 32x64, mma.sync.m16n8k8.tf32
// EPI 0: +bias   1: gelu(+bias)   2: +bias+add
template<int EPI>
__global__ void __launch_bounds__(256) tgemm_nt(const float* __restrict__ A,
    const float* __restrict__ W, const float* __restrict__ bias,
    const float* __restrict__ add, float* __restrict__ C, int Nc, int K)
{
    __shared__ unsigned As[16][136];
    __shared__ unsigned Bs[16][136];
    int tid=threadIdx.x;
    int wid=tid>>5, lane=tid&31;
    int wm=(wid&3)*32, wn=(wid>>2)*64;
    int gid=lane>>2, tg=lane&3;
    int bm=blockIdx.y*128, bn=blockIdx.x*128;
    int lrow=tid>>1, lcol=(tid&1)*8;
    const float* Ap=A+(size_t)(bm+lrow)*K+lcol;
    const float* Wp=W+(size_t)(bn+lrow)*K+lcol;

    float acc[2][8][4];
    #pragma unroll
    for(int f=0;f<2;f++)
        #pragma unroll
        for(int j=0;j<8;j++)
            #pragma unroll
            for(int q=0;q<4;q++) acc[f][j][q]=0.f;

    float4 a0=*(const float4*)(Ap),   a1=*(const float4*)(Ap+4);
    float4 w0=*(const float4*)(Wp),   w1=*(const float4*)(Wp+4);

    for(int k0=0;k0<K;k0+=16){
        As[lcol+0][lrow]=f2tf(a0.x); As[lcol+1][lrow]=f2tf(a0.y);
        As[lcol+2][lrow]=f2tf(a0.z); As[lcol+3][lrow]=f2tf(a0.w);
        As[lcol+4][lrow]=f2tf(a1.x); As[lcol+5][lrow]=f2tf(a1.y);
        As[lcol+6][lrow]=f2tf(a1.z); As[lcol+7][lrow]=f2tf(a1.w);
        Bs[lcol+0][lrow]=f2tf(w0.x); Bs[lcol+1][lrow]=f2tf(w0.y);
        Bs[lcol+2][lrow]=f2tf(w0.z); Bs[lcol+3][lrow]=f2tf(w0.w);
        Bs[lcol+4][lrow]=f2tf(w1.x); Bs[lcol+5][lrow]=f2tf(w1.y);
        Bs[lcol+6][lrow]=f2tf(w1.z); Bs[lcol+7][lrow]=f2tf(w1.w);
        __syncthreads();
        if(k0+16<K){
            a0=*(const float4*)(Ap+k0+16); a1=*(const float4*)(Ap+k0+20);
            w0=*(const float4*)(Wp+k0+16); w1=*(const float4*)(Wp+k0+20);
        }
        #pragma unroll
        for(int kk=0;kk<16;kk+=8){
            unsigned af[2][4];
            #pragma unroll
            for(int f=0;f<2;f++){
                int m=wm+f*16+gid;
                af[f][0]=As[kk+tg  ][m];
                af[f][1]=As[kk+tg  ][m+8];
                af[f][2]=As[kk+tg+4][m];
                af[f][3]=As[kk+tg+4][m+8];
            }
            #pragma unroll
            for(int j=0;j<8;j++){
                unsigned b0=Bs[kk+tg  ][wn+j*8+gid];
                unsigned b1=Bs[kk+tg+4][wn+j*8+gid];
                #pragma unroll
                for(int f=0;f<2;f++){
                    asm volatile(
                      "mma.sync.aligned.m16n8k8.row.col.f32.tf32.tf32.f32 "
                      "{%0,%1,%2,%3}, {%4,%5,%6,%7}, {%8,%9}, {%0,%1,%2,%3};\n"
                      : "+f"(acc[f][j][0]),"+f"(acc[f][j][1]),
                        "+f"(acc[f][j][2]),"+f"(acc[f][j][3])
                      : "r"(af[f][0]),"r"(af[f][1]),"r"(af[f][2]),"r"(af[f][3]),
                        "r"(b0),"r"(b1));
                }
            }
        }
        __syncthreads();
    }

    #pragma unroll
    for(int f=0;f<2;f++){
        int r0=bm+wm+f*16+gid;
        #pragma unroll
        for(int j=0;j<8;j++){
            int col=bn+wn+j*8+tg*2;
            float2 bv=*(const float2*)(bias+col);
            float2 v0, v1;
            v0.x=acc[f][j][0]+bv.x; v0.y=acc[f][j][1]+bv.y;
            v1.x=acc[f][j][2]+bv.x; v1.y=acc[f][j][3]+bv.y;
            if(EPI==1){
                v0.x=gelu_f(v0.x); v0.y=gelu_f(v0.y);
                v1.x=gelu_f(v1.x); v1.y=gelu_f(v1.y);
            }
            if(EPI==2){
                float2 e0=*(const float2*)(add+(size_t)r0*Nc+col);
                float2 e1=*(const float2*)(add+(size_t)(r0+8)*Nc+col);
                v0.x+=e0.x; v0.y+=e0.y; v1.x+=e1.x; v1.y+=e1.y;
            }
            *(float2*)(C+(size_t)r0*Nc+col)=v0;
            *(float2*)(C+(size_t)(r0+8)*Nc+col)=v1;
        }
    }
}

// ---------- ref tokens: (x_ref @ ref_qk_w^T + b), reparam -> g_refq/g_refv ----------
__global__ void __launch_bounds__(256) refqk(const float* __restrict__ xr,
    const float* __restrict__ Wt, const float* __restrict__ bias,
    const float* __restrict__ dmu, const float* __restrict__ dls)
{
    __shared__ __align__(16) float xs[512];
    int row=blockIdx.x, tid=threadIdx.x;
    int rb=row/100, r=row-100*rb;
    const float* src=xr+(size_t)row*512;
    xs[tid]=src[tid]; xs[tid+256]=src[tid+256];
    __syncthreads();
    const float4* x4=(const float4*)xs;
    for(int rep=0;rep<4;rep++){
        int col=tid+rep*256;
        const float4* w4=(const float4*)(Wt+(size_t)col*512);
        float acc=bias[col];
        #pragma unroll 8
        for(int k=0;k<128;k++){
            float4 a=x4[k], b=w4[k];
            acc+=a.x*b.x+a.y*b.y+a.z*b.z+a.w*b.w;
        }
        if(col<512){
            int h=col>>5, d=col&31;
            g_refq[(((size_t)rb*16+h)*100+r)*32+d]=dmu[col]+expf(dls[col])*acc;
        }else{
            int cc=col-512, h=cc>>5, d=cc&31;
            g_refv[(((size_t)rb*16+h)*100+r)*32+d]=acc;
        }
    }
}

// ---------- ra = q @ ref_q^T per (window, head) -> conv layout ----------
__global__ void __launch_bounds__(256) ra_kernel()
{
    __shared__ float qs[1568];
    __shared__ float rs[3300];   // 100 rows, stride 33
    int bx=blockIdx.x, tid=threadIdx.x;
    int win=bx>>4, h=bx&15, rb=win>>8, winb=win&255;
    for(int i=tid;i<1568;i+=256){
        int n=i>>5, d=i&31;
        qs[i]=g_qkv[(size_t)(win*49+n)*1536 + h*32 + d];
    }
    const float* rq = g_refq + (size_t)(rb*16+h)*3200;
    for(int i=tid;i<3200;i+=256){
        int r=i>>5, d=i&31;
        rs[r*33+d]=rq[i];
    }
    __syncthreads();
    float* out = g_ra + ((size_t)(rb*16+h)*RH + winb*49)*100;
    for(int idx=tid;idx<4900;idx+=256){
        int n=idx/100, r=idx-100*n;
        const float* q=qs+n*32; const float* rr=rs+r*33;
        float acc=0.f;
        #pragma unroll
        for(int k=0;k<32;k++) acc+=q[k]*rr[k];
        out[idx]=acc;
    }
}

// ---------- conv diffusion ----------
__global__ void zero_stats(){
    if(threadIdx.x<32){ g_ss[threadIdx.x]=0.0; g_sq[threadIdx.x]=0.0; }
}

__global__ void __launch_bounds__(256) conv3x3(const float* __restrict__ cw,
    const float* __restrict__ cb)
{
    __shared__ float s_in[16][4][102];
    __shared__ __align__(16) float s_w[2304];   // [(ci*9+tap)*16+co]
    __shared__ float red_s[8][16], red_q[8][16];
    int tid=threadIdx.y*128+threadIdx.x;
    int h0=blockIdx.x*2, nb=blockIdx.y;
    for(int i=tid;i<2304;i+=256){
        int ci=i/144, t2=i-144*ci, tap=t2>>4, co=t2&15;
        s_w[i]=cw[(co*16+ci)*9+tap];
    }
    for(int i=tid;i<6528;i+=256){
        int ci=i/408, t2=i-408*ci, rr=t2/102, cc=t2-102*rr;
        int gr=h0-1+rr, gc=cc-1;
        float v=0.f;
        if(gr>=0 && gr<RH && gc>=0 && gc<100)
            v=g_ra[((size_t)(nb*16+ci)*RH+gr)*100+gc];
        s_in[ci][rr][cc]=v;
    }
    __syncthreads();
    int w=threadIdx.x, y=threadIdx.y;
    bool act=(w<100);
    float acc[16];
    #pragma unroll
    for(int co=0;co<16;co++) acc[co]=cb[co];
    if(act){
        #pragma unroll 4
        for(int ci=0;ci<16;ci++){
            #pragma unroll
            for(int dr=0;dr<3;dr++){
                #pragma unroll
                for(int dc=0;dc<3;dc++){
                    float v=s_in[ci][y+dr][w+dc];
                    const float4* wp=(const float4*)&s_w[(ci*9+dr*3+dc)*16];
                    #pragma unroll
                    for(int q=0;q<4;q++){
                        float4 ww=wp[q];
                        acc[q*4+0]+=ww.x*v; acc[q*4+1]+=ww.y*v;
                        acc[q*4+2]+=ww.z*v; acc[q*4+3]+=ww.w*v;
                    }
                }
            }
        }
        int hh=h0+y;
        #pragma unroll
        for(int co=0;co<16;co++)
            g_u[((size_t)(nb*16+co)*RH+hh)*100+w]=acc[co];
    }
    int wp2=tid>>5, lane=tid&31;
    #pragma unroll
    for(int co=0;co<16;co++){
        float s=act?acc[co]:0.f;
        float q=s*s;
        #pragma unroll
        for(int o=16;o;o>>=1){ s+=__shfl_xor_sync(~0u,s,o); q+=__shfl_xor_sync(~0u,q,o); }
        if(lane==0){ red_s[wp2][co]=s; red_q[wp2][co]=q; }
    }
    __syncthreads();
    if(tid<16){
        float S=0.f,Q=0.f;
        #pragma unroll
        for(int i=0;i<8;i++){ S+=red_s[i][tid]; Q+=red_q[i][tid]; }
        atomicAdd(&g_ss[nb*16+tid],(double)S);
        atomicAdd(&g_sq[nb*16+tid],(double)Q);
    }
}

__global__ void __launch_bounds__(256) norm_gelu()
{
    int p=blockIdx.y;
    size_t base=(size_t)p*PLANE + (size_t)blockIdx.x*256 + threadIdx.x;
    double cnt=1254400.0;
    double mu=g_ss[p]/cnt;
    double var=g_sq[p]/cnt - mu*mu;
    float rs=(float)rsqrt(var+1e-5);
    float m=(float)mu;
    float u=g_u[base];
    g_ra[base]+=gelu_f((u-m)*rs);
}

// ---------- fused attention per (window, head) ----------
__global__ void __launch_bounds__(256) attn_kernel(const float* __restrict__ mask,
    const float* __restrict__ rpb)
{
    __shared__ float A[4900];   // ra (49x100) -> scores (49 rows, stride 50)
    __shared__ float B[3200];   // refv (stride 32) -> k (stride 33)
    __shared__ float Q[1568];   // q_new (stride 32)
    __shared__ float V[1617];   // v (stride 33)
    int bx=blockIdx.x, tid=threadIdx.x;
    int win=bx>>4, h=bx&15, rb=win>>8, winb=win&255;
    int plane=rb*16+h;
    const float* raP=g_ra + ((size_t)plane*RH + winb*49)*100;
    for(int i=tid;i<4900;i+=256) A[i]=raP[i];
    const float* rvP=g_refv + (size_t)plane*3200;
    for(int i=tid;i<3200;i+=256) B[i]=rvP[i];
    for(int i=tid;i<1568;i+=256){
        int n=i>>5, d=i&31;
        V[n*33+d]=g_qkv[(size_t)(win*49+n)*1536 + 1024 + h*32 + d];
    }
    __syncthreads();
    int wp=tid>>5, lane=tid&31;
    // softmax over 100 per row
    for(int n=wp;n<49;n+=8){
        float* row=A+n*100;
        float e0=row[lane], e1=row[lane+32], e2=row[lane+64];
        float e3=(lane<4)?row[lane+96]:-1e30f;
        float m=fmaxf(fmaxf(e0,e1),fmaxf(e2,e3));
        #pragma unroll
        for(int o=16;o;o>>=1) m=fmaxf(m,__shfl_xor_sync(~0u,m,o));
        e0=__expf(e0-m); e1=__expf(e1-m); e2=__expf(e2-m);
        e3=(lane<4)?__expf(e3-m):0.f;
        float s=e0+e1+e2+e3;
        #pragma unroll
        for(int o=16;o;o>>=1) s+=__shfl_xor_sync(~0u,s,o);
        float inv=1.f/s;
        row[lane]=e0*inv; row[lane+32]=e1*inv; row[lane+64]=e2*inv;
        if(lane<4) row[lane+96]=e3*inv;
    }
    __syncthreads();
    // q_new = ra @ refv * SCALE
    for(int idx=tid;idx<1568;idx+=256){
        int n=idx>>5, d=idx&31;
        float acc=0.f; const float* ar=A+n*100;
        #pragma unroll 4
        for(int r=0;r<100;r++) acc+=ar[r]*B[r*32+d];
        Q[idx]=acc*SCALEV;
    }
    __syncthreads();
    // load k into B (stride 33)
    for(int i=tid;i<1568;i+=256){
        int n=i>>5, d=i&31;
        B[n*33+d]=g_qkv[(size_t)(win*49+n)*1536 + 512 + h*32 + d];
    }
    __syncthreads();
    // scores = q_new @ k^T + rpb + mask  (into A, stride 50)
    const float* mrow=mask + (size_t)winb*2401;
    for(int idx=tid;idx<2401;idx+=256){
        int n=idx/49, m2=idx-49*n;
        float acc=0.f; const float* qr=Q+n*32; const float* kr=B+m2*33;
        #pragma unroll
        for(int k=0;k<32;k++) acc+=qr[k]*kr[k];
        int rpi=(n/7 - m2/7 + 6)*13 + (n%7 - m2%7 + 6);
        acc += rpb[rpi*16+h] + mrow[idx];
        A[n*50+m2]=acc;
    }
    __syncthreads();
    // softmax over 49 per row
    for(int n=wp;n<49;n+=8){
        float* row=A+n*50;
        float a0=row[lane];
        float a1=(lane<17)?row[lane+32]:-1e30f;
        float m=fmaxf(a0,a1);
        #pragma unroll
        for(int o=16;o;o>>=1) m=fmaxf(m,__shfl_xor_sync(~0u,m,o));
        a0=__expf(a0-m);
        a1=(lane<17)?__expf(a1-m):0.f;
        float s=a0+a1;
        #pragma unroll
        for(int o=16;o;o>>=1) s+=__shfl_xor_sync(~0u,s,o);
        float inv=1.f/s;
        row[lane]=a0*inv; if(lane<17) row[lane+32]=a1*inv;
    }
    __syncthreads();
    // out = attn @ v -> (token, h*32+d) layout
    for(int idx=tid;idx<1568;idx+=256){
        int n=idx>>5, d=idx&31;
        float acc=0.f; const float* sr=A+n*50;
        #pragma unroll 7
        for(int m2=0;m2<49;m2++) acc+=sr[m2]*V[m2*33+d];
        g_ao[(size_t)(win*49+n)*512 + h*32 + d]=acc;
    }
}

// ---------- window reverse + roll(+3,+3) + residual + LN2 ----------
__global__ void __launch_bounds__(256) rev_ln2(const float* __restrict__ x,
    const float* __restrict__ w, const float* __restrict__ b)
{
    int t=blockIdx.x, tid=threadIdx.x;
    int bb=t/LTOK, rem=t-bb*LTOK;
    int hh=rem/112, ww=rem-112*hh;
    int hs=hh+109; if(hs>=112) hs-=112;
    int ws=ww+109; if(ws>=112) ws-=112;
    int win=bb*256 + (hs/7)*16 + (ws/7);
    int n=(hs%7)*7 + (ws%7);
    const float* pr=g_proj + (size_t)(win*49+n)*512;
    const float* xr=x + (size_t)t*512;
    float v0=xr[tid]+pr[tid], v1=xr[tid+256]+pr[tid+256];
    float mu,rs; ln_stats(v0,v1,mu,rs);
    float* o2=g_x2 + (size_t)t*512;
    float* ol=g_ln2 + (size_t)t*512;
    o2[tid]=v0; o2[tid+256]=v1;
    ol[tid]    =(v0-mu)*rs*w[tid]    +b[tid];
    ol[tid+256]=(v1-mu)*rs*w[tid+256]+b[tid+256];
}

// ---------- launch ----------
extern "C" void kernel_launch(void* const* d_in, const int* in_sizes, int n_in,
                              void* d_out, int out_size)
{
    const float* x    =(const float*)d_in[0];
    const float* x_ref=(const float*)d_in[1];
    const float* mask =(const float*)d_in[2];
    const float* n1w  =(const float*)d_in[3];
    const float* n1b  =(const float*)d_in[4];
    const float* qkvw =(const float*)d_in[5];
    const float* qkvb =(const float*)d_in[6];
    const float* dmu  =(const float*)d_in[7];
    const float* dls  =(const float*)d_in[8];
    const float* rpb  =(const float*)d_in[9];
    const float* rqw  =(const float*)d_in[10];
    const float* rqb  =(const float*)d_in[11];
    const float* cw   =(const float*)d_in[12];
    const float* cb   =(const float*)d_in[13];
    const float* pw   =(const float*)d_in[14];
    const float* pb   =(const float*)d_in[15];
    const float* n2w  =(const float*)d_in[16];
    const float* n2b  =(const float*)d_in[17];
    const float* f1w  =(const float*)d_in[18];
    const float* f1b  =(const float*)d_in[19];
    const float* f2w  =(const float*)d_in[20];
    const float* f2b  =(const float*)d_in[21];
    float* out=(float*)d_out;
    (void)in_sizes; (void)n_in; (void)out_size;

    float *p_xw, *p_qkv, *p_ao, *p_proj, *p_ln2, *p_fc1, *p_x2;
    cudaGetSymbolAddress((void**)&p_xw,  g_xw);
    cudaGetSymbolAddress((void**)&p_qkv, g_qkv);
    cudaGetSymbolAddress((void**)&p_ao,  g_ao);
    cudaGetSymbolAddress((void**)&p_proj,g_proj);
    cudaGetSymbolAddress((void**)&p_ln2, g_ln2);
    cudaGetSymbolAddress((void**)&p_fc1, g_fc1);
    cudaGetSymbolAddress((void**)&p_x2,  g_x2);

    ln1_shift<<<TTOK,256>>>(x, n1w, n1b);
    tgemm_nt<0><<<dim3(12,196),256>>>(p_xw, qkvw, qkvb, nullptr, p_qkv, 1536, 512);
    refqk<<<200,256>>>(x_ref, rqw, rqb, dmu, dls);
    ra_kernel<<<8192,256>>>();
    for(int it=0; it<3; it++){
        zero_stats<<<1,32>>>();
        conv3x3<<<dim3(6272,2),dim3(128,2)>>>(cw, cb);
        norm_gelu<<<dim3(4900,32),256>>>();
    }
    attn_kernel<<<8192,256>>>(mask, rpb);
    tgemm_nt<0><<<dim3(4,196),256>>>(p_ao, pw, pb, nullptr, p_proj, 512, 512);
    rev_ln2<<<TTOK,256>>>(x, n2w, n2b);
    tgemm_nt<1><<<dim3(16,196),256>>>(p_ln2, f1w, f1b, nullptr, p_fc1, 2048, 512);
    tgemm_nt<2><<<dim3(4,196),256>>>(p_fc1, f2w, f2b, p_x2, out, 512, 2048);
}

// round 11
// speedup vs baseline: 2.4664x; 2.0767x over previous
#include <cuda_runtime.h>
#include <math.h>

#define HEADS 16
#define HD    32
#define CDIM  512
#define NREF  100
#define LTOK  12544
#define TTOK  25088
#define RH    12544
#define RW    100
#define PLANE ((size_t)RH*RW)
#define EPSV  1e-5f
#define SCALEV 0.17677669529663687f

// ---------- scratch ----------
static __device__ float g_xw [(size_t)TTOK*CDIM];
static __device__ float g_qkv[(size_t)TTOK*3*CDIM];
static __device__ float g_refq[2*HEADS*NREF*HD];
static __device__ float g_refv[2*HEADS*NREF*HD];
static __device__ float g_ra [(size_t)32*PLANE];
static __device__ float g_u  [(size_t)32*PLANE];
static __device__ float g_ao [(size_t)TTOK*CDIM];
static __device__ float g_proj[(size_t)TTOK*CDIM];
static __device__ float g_x2 [(size_t)TTOK*CDIM];
static __device__ float g_ln2[(size_t)TTOK*CDIM];
static __device__ float g_fc1[(size_t)TTOK*4*CDIM];
static __device__ double g_ss[32], g_sq[32];
static __device__ float g_mu[32], g_rsd[32];

__device__ __forceinline__ float gelu_f(float x){
    return 0.5f*x*(1.f+erff(x*0.70710678118654752f));
}

__device__ __forceinline__ unsigned f2tf(float f){
    unsigned u; asm("cvt.rna.tf32.f32 %0, %1;" : "=r"(u) : "f"(f)); return u;
}

// block-wide LN stats for a 512-wide row held as (v0,v1) per thread (256 threads)
__device__ __forceinline__ void ln_stats(float v0, float v1, float& mu, float& rs){
    __shared__ float r1[8], r2[8];
    __shared__ float smu, srs;
    float s=v0+v1, q=v0*v0+v1*v1;
    #pragma unroll
    for(int o=16;o;o>>=1){ s+=__shfl_xor_sync(~0u,s,o); q+=__shfl_xor_sync(~0u,q,o); }
    int tid=threadIdx.x;
    if((tid&31)==0){ r1[tid>>5]=s; r2[tid>>5]=q; }
    __syncthreads();
    if(tid==0){
        float S=0.f,Q=0.f;
        #pragma unroll
        for(int i=0;i<8;i++){S+=r1[i];Q+=r2[i];}
        float m=S*(1.f/512.f);
        smu=m; srs=rsqrtf(Q*(1.f/512.f)-m*m+EPSV);
    }
    __syncthreads();
    mu=smu; rs=srs;
}

// ---------- LN1 + shift(-3,-3) + window partition -> g_xw ----------
__global__ void __launch_bounds__(256) ln1_shift(const float* __restrict__ x,
    const float* __restrict__ w, const float* __restrict__ b)
{
    int t=blockIdx.x, tid=threadIdx.x;
    int win=t/49, n=t-49*win;
    int bb=win>>8, wi=win&255;
    int r=n/7, c=n-7*r;
    int hs=(wi>>4)*7 + r + 3; if(hs>=112) hs-=112;
    int ws=(wi&15)*7 + c + 3; if(ws>=112) ws-=112;
    const float* xr = x + ((size_t)bb*LTOK + hs*112 + ws)*CDIM;
    float v0=xr[tid], v1=xr[tid+256];
    float mu,rs; ln_stats(v0,v1,mu,rs);
    float* o = g_xw + (size_t)t*CDIM;
    o[tid]      =(v0-mu)*rs*w[tid]      +b[tid];
    o[tid+256]  =(v1-mu)*rs*w[tid+256]  +b[tid+256];
}

// ---------- TF32 tensor-core NT GEMM: C[M,Nc]=A[M,K]@W[Nc,K]^T (+epilogue) ----------
// EPI 0: +bias   1: gelu(+bias)   2: +bias+add
template<int EPI>
__global__ void __launch_bounds__(256) tgemm_nt(const float* __restrict__ A,
    const float* __restrict__ W, const float* __restrict__ bias,
    const float* __restrict__ add, float* __restrict__ C, int Nc, int K)
{
    __shared__ unsigned As[16][136];
    __shared__ unsigned Bs[16][136];
    int tid=threadIdx.x;
    int wid=tid>>5, lane=tid&31;
    int wm=(wid&3)*32, wn=(wid>>2)*64;
    int gid=lane>>2, tg=lane&3;
    int bm=blockIdx.y*128, bn=blockIdx.x*128;
    int lrow=tid>>1, lcol=(tid&1)*8;
    const float* Ap=A+(size_t)(bm+lrow)*K+lcol;
    const float* Wp=W+(size_t)(bn+lrow)*K+lcol;

    float acc[2][8][4];
    #pragma unroll
    for(int f=0;f<2;f++)
        #pragma unroll
        for(int j=0;j<8;j++)
            #pragma unroll
            for(int q=0;q<4;q++) acc[f][j][q]=0.f;

    float4 a0=*(const float4*)(Ap),   a1=*(const float4*)(Ap+4);
    float4 w0=*(const float4*)(Wp),   w1=*(const float4*)(Wp+4);

    for(int k0=0;k0<K;k0+=16){
        As[lcol+0][lrow]=f2tf(a0.x); As[lcol+1][lrow]=f2tf(a0.y);
        As[lcol+2][lrow]=f2tf(a0.z); As[lcol+3][lrow]=f2tf(a0.w);
        As[lcol+4][lrow]=f2tf(a1.x); As[lcol+5][lrow]=f2tf(a1.y);
        As[lcol+6][lrow]=f2tf(a1.z); As[lcol+7][lrow]=f2tf(a1.w);
        Bs[lcol+0][lrow]=f2tf(w0.x); Bs[lcol+1][lrow]=f2tf(w0.y);
        Bs[lcol+2][lrow]=f2tf(w0.z); Bs[lcol+3][lrow]=f2tf(w0.w);
        Bs[lcol+4][lrow]=f2tf(w1.x); Bs[lcol+5][lrow]=f2tf(w1.y);
        Bs[lcol+6][lrow]=f2tf(w1.z); Bs[lcol+7][lrow]=f2tf(w1.w);
        __syncthreads();
        if(k0+16<K){
            a0=*(const float4*)(Ap+k0+16); a1=*(const float4*)(Ap+k0+20);
            w0=*(const float4*)(Wp+k0+16); w1=*(const float4*)(Wp+k0+20);
        }
        #pragma unroll
        for(int kk=0;kk<16;kk+=8){
            unsigned af[2][4];
            #pragma unroll
            for(int f=0;f<2;f++){
                int m=wm+f*16+gid;
                af[f][0]=As[kk+tg  ][m];
                af[f][1]=As[kk+tg  ][m+8];
                af[f][2]=As[kk+tg+4][m];
                af[f][3]=As[kk+tg+4][m+8];
            }
            #pragma unroll
            for(int j=0;j<8;j++){
                unsigned b0=Bs[kk+tg  ][wn+j*8+gid];
                unsigned b1=Bs[kk+tg+4][wn+j*8+gid];
                #pragma unroll
                for(int f=0;f<2;f++){
                    asm volatile(
                      "mma.sync.aligned.m16n8k8.row.col.f32.tf32.tf32.f32 "
                      "{%0,%1,%2,%3}, {%4,%5,%6,%7}, {%8,%9}, {%0,%1,%2,%3};\n"
                      : "+f"(acc[f][j][0]),"+f"(acc[f][j][1]),
                        "+f"(acc[f][j][2]),"+f"(acc[f][j][3])
                      : "r"(af[f][0]),"r"(af[f][1]),"r"(af[f][2]),"r"(af[f][3]),
                        "r"(b0),"r"(b1));
                }
            }
        }
        __syncthreads();
    }

    #pragma unroll
    for(int f=0;f<2;f++){
        int r0=bm+wm+f*16+gid;
        #pragma unroll
        for(int j=0;j<8;j++){
            int col=bn+wn+j*8+tg*2;
            float2 bv=*(const float2*)(bias+col);
            float2 v0, v1;
            v0.x=acc[f][j][0]+bv.x; v0.y=acc[f][j][1]+bv.y;
            v1.x=acc[f][j][2]+bv.x; v1.y=acc[f][j][3]+bv.y;
            if(EPI==1){
                v0.x=gelu_f(v0.x); v0.y=gelu_f(v0.y);
                v1.x=gelu_f(v1.x); v1.y=gelu_f(v1.y);
            }
            if(EPI==2){
                float2 e0=*(const float2*)(add+(size_t)r0*Nc+col);
                float2 e1=*(const float2*)(add+(size_t)(r0+8)*Nc+col);
                v0.x+=e0.x; v0.y+=e0.y; v1.x+=e1.x; v1.y+=e1.y;
            }
            *(float2*)(C+(size_t)r0*Nc+col)=v0;
            *(float2*)(C+(size_t)(r0+8)*Nc+col)=v1;
        }
    }
}

// ---------- ref tokens ----------
__global__ void __launch_bounds__(256) refqk(const float* __restrict__ xr,
    const float* __restrict__ Wt, const float* __restrict__ bias,
    const float* __restrict__ dmu, const float* __restrict__ dls)
{
    __shared__ __align__(16) float xs[512];
    int row=blockIdx.x, tid=threadIdx.x;
    int rb=row/100, r=row-100*rb;
    const float* src=xr+(size_t)row*512;
    xs[tid]=src[tid]; xs[tid+256]=src[tid+256];
    __syncthreads();
    const float4* x4=(const float4*)xs;
    for(int rep=0;rep<4;rep++){
        int col=tid+rep*256;
        const float4* w4=(const float4*)(Wt+(size_t)col*512);
        float acc=bias[col];
        #pragma unroll 8
        for(int k=0;k<128;k++){
            float4 a=x4[k], b=w4[k];
            acc+=a.x*b.x+a.y*b.y+a.z*b.z+a.w*b.w;
        }
        if(col<512){
            int h=col>>5, d=col&31;
            g_refq[(((size_t)rb*16+h)*100+r)*32+d]=dmu[col]+expf(dls[col])*acc;
        }else{
            int cc=col-512, h=cc>>5, d=cc&31;
            g_refv[(((size_t)rb*16+h)*100+r)*32+d]=acc;
        }
    }
}

// ---------- ra = q @ ref_q^T per (window, head) -> conv layout ----------
__global__ void __launch_bounds__(256) ra_kernel()
{
    __shared__ float qs[1568];
    __shared__ float rs[3300];   // 100 rows, stride 33
    int bx=blockIdx.x, tid=threadIdx.x;
    int win=bx>>4, h=bx&15, rb=win>>8, winb=win&255;
    for(int i=tid;i<1568;i+=256){
        int n=i>>5, d=i&31;
        qs[i]=g_qkv[(size_t)(win*49+n)*1536 + h*32 + d];
    }
    const float* rq = g_refq + (size_t)(rb*16+h)*3200;
    for(int i=tid;i<3200;i+=256){
        int r=i>>5, d=i&31;
        rs[r*33+d]=rq[i];
    }
    __syncthreads();
    float* out = g_ra + ((size_t)(rb*16+h)*RH + winb*49)*100;
    for(int idx=tid;idx<4900;idx+=256){
        int n=idx/100, r=idx-100*n;
        const float* q=qs+n*32; const float* rr=rs+r*33;
        float acc=0.f;
        #pragma unroll
        for(int k=0;k<32;k++) acc+=q[k]*rr[k];
        out[idx]=acc;
    }
}

// ---------- conv diffusion ----------
__global__ void zero_stats(){
    if(threadIdx.x<32){ g_ss[threadIdx.x]=0.0; g_sq[threadIdx.x]=0.0; }
}

__global__ void __launch_bounds__(256) conv3x3(const float* __restrict__ cw,
    const float* __restrict__ cb)
{
    __shared__ float s_in[16][4][102];
    __shared__ __align__(16) float s_w[2304];   // [(ci*9+tap)*16+co]
    __shared__ float red_s[8][16], red_q[8][16];
    int tid=threadIdx.y*128+threadIdx.x;
    int h0=blockIdx.x*2, nb=blockIdx.y;
    for(int i=tid;i<2304;i+=256){
        int ci=i/144, t2=i-144*ci, tap=t2>>4, co=t2&15;
        s_w[i]=cw[(co*16+ci)*9+tap];
    }
    for(int i=tid;i<6528;i+=256){
        int ci=i/408, t2=i-408*ci, rr=t2/102, cc=t2-102*rr;
        int gr=h0-1+rr, gc=cc-1;
        float v=0.f;
        if(gr>=0 && gr<RH && gc>=0 && gc<100)
            v=g_ra[((size_t)(nb*16+ci)*RH+gr)*100+gc];
        s_in[ci][rr][cc]=v;
    }
    __syncthreads();
    int w=threadIdx.x, y=threadIdx.y;
    bool act=(w<100);
    float acc[16];
    #pragma unroll
    for(int co=0;co<16;co++) acc[co]=cb[co];
    if(act){
        #pragma unroll 4
        for(int ci=0;ci<16;ci++){
            #pragma unroll
            for(int dr=0;dr<3;dr++){
                #pragma unroll
                for(int dc=0;dc<3;dc++){
                    float v=s_in[ci][y+dr][w+dc];
                    const float4* wp=(const float4*)&s_w[(ci*9+dr*3+dc)*16];
                    #pragma unroll
                    for(int q=0;q<4;q++){
                        float4 ww=wp[q];
                        acc[q*4+0]+=ww.x*v; acc[q*4+1]+=ww.y*v;
                        acc[q*4+2]+=ww.z*v; acc[q*4+3]+=ww.w*v;
                    }
                }
            }
        }
        int hh=h0+y;
        #pragma unroll
        for(int co=0;co<16;co++)
            g_u[((size_t)(nb*16+co)*RH+hh)*100+w]=acc[co];
    }
    int wp2=tid>>5, lane=tid&31;
    #pragma unroll
    for(int co=0;co<16;co++){
        float s=act?acc[co]:0.f;
        float q=s*s;
        #pragma unroll
        for(int o=16;o;o>>=1){ s+=__shfl_xor_sync(~0u,s,o); q+=__shfl_xor_sync(~0u,q,o); }
        if(lane==0){ red_s[wp2][co]=s; red_q[wp2][co]=q; }
    }
    __syncthreads();
    if(tid<16){
        float S=0.f,Q=0.f;
        #pragma unroll
        for(int i=0;i<8;i++){ S+=red_s[i][tid]; Q+=red_q[i][tid]; }
        atomicAdd(&g_ss[nb*16+tid],(double)S);
        atomicAdd(&g_sq[nb*16+tid],(double)Q);
    }
}

// per-plane stats -> float mu / rstd (fp64 confined to 32 threads)
__global__ void finalize_stats(){
    int p=threadIdx.x;
    if(p<32){
        double cnt=1254400.0;
        double mu=g_ss[p]/cnt;
        double var=g_sq[p]/cnt - mu*mu;
        g_mu[p]=(float)mu;
        g_rsd[p]=(float)rsqrt(var+1e-5);
    }
}

// pure fp32, float4-vectorized: g_ra += gelu((g_u - mu)*rstd)
__global__ void __launch_bounds__(256) norm_gelu()
{
    int p=blockIdx.y;
    float m=g_mu[p], rs=g_rsd[p];
    size_t base=(size_t)p*PLANE + (((size_t)blockIdx.x*256 + threadIdx.x)<<2);
    float4 u=*(const float4*)(g_u+base);
    float4 r=*(const float4*)(g_ra+base);
    r.x+=gelu_f((u.x-m)*rs);
    r.y+=gelu_f((u.y-m)*rs);
    r.z+=gelu_f((u.z-m)*rs);
    r.w+=gelu_f((u.w-m)*rs);
    *(float4*)(g_ra+base)=r;
}

// ---------- fused attention per (window, head) ----------
__global__ void __launch_bounds__(256) attn_kernel(const float* __restrict__ mask,
    const float* __restrict__ rpb)
{
    __shared__ float A[4900];   // ra (49x100) -> scores (49 rows, stride 50)
    __shared__ float B[3200];   // refv (stride 32) -> k (stride 33)
    __shared__ float Q[1568];   // q_new (stride 32)
    __shared__ float V[1617];   // v (stride 33)
    int bx=blockIdx.x, tid=threadIdx.x;
    int win=bx>>4, h=bx&15, rb=win>>8, winb=win&255;
    int plane=rb*16+h;
    const float* raP=g_ra + ((size_t)plane*RH + winb*49)*100;
    for(int i=tid;i<4900;i+=256) A[i]=raP[i];
    const float* rvP=g_refv + (size_t)plane*3200;
    for(int i=tid;i<3200;i+=256) B[i]=rvP[i];
    for(int i=tid;i<1568;i+=256){
        int n=i>>5, d=i&31;
        V[n*33+d]=g_qkv[(size_t)(win*49+n)*1536 + 1024 + h*32 + d];
    }
    __syncthreads();
    int wp=tid>>5, lane=tid&31;
    // softmax over 100 per row
    for(int n=wp;n<49;n+=8){
        float* row=A+n*100;
        float e0=row[lane], e1=row[lane+32], e2=row[lane+64];
        float e3=(lane<4)?row[lane+96]:-1e30f;
        float m=fmaxf(fmaxf(e0,e1),fmaxf(e2,e3));
        #pragma unroll
        for(int o=16;o;o>>=1) m=fmaxf(m,__shfl_xor_sync(~0u,m,o));
        e0=__expf(e0-m); e1=__expf(e1-m); e2=__expf(e2-m);
        e3=(lane<4)?__expf(e3-m):0.f;
        float s=e0+e1+e2+e3;
        #pragma unroll
        for(int o=16;o;o>>=1) s+=__shfl_xor_sync(~0u,s,o);
        float inv=1.f/s;
        row[lane]=e0*inv; row[lane+32]=e1*inv; row[lane+64]=e2*inv;
        if(lane<4) row[lane+96]=e3*inv;
    }
    __syncthreads();
    // q_new = ra @ refv * SCALE
    for(int idx=tid;idx<1568;idx+=256){
        int n=idx>>5, d=idx&31;
        float acc=0.f; const float* ar=A+n*100;
        #pragma unroll 4
        for(int r=0;r<100;r++) acc+=ar[r]*B[r*32+d];
        Q[idx]=acc*SCALEV;
    }
    __syncthreads();
    // load k into B (stride 33)
    for(int i=tid;i<1568;i+=256){
        int n=i>>5, d=i&31;
        B[n*33+d]=g_qkv[(size_t)(win*49+n)*1536 + 512 + h*32 + d];
    }
    __syncthreads();
    // scores = q_new @ k^T + rpb + mask  (into A, stride 50)
    const float* mrow=mask + (size_t)winb*2401;
    for(int idx=tid;idx<2401;idx+=256){
        int n=idx/49, m2=idx-49*n;
        float acc=0.f; const float* qr=Q+n*32; const float* kr=B+m2*33;
        #pragma unroll
        for(int k=0;k<32;k++) acc+=qr[k]*kr[k];
        int rpi=(n/7 - m2/7 + 6)*13 + (n%7 - m2%7 + 6);
        acc += rpb[rpi*16+h] + mrow[idx];
        A[n*50+m2]=acc;
    }
    __syncthreads();
    // softmax over 49 per row
    for(int n=wp;n<49;n+=8){
        float* row=A+n*50;
        float a0=row[lane];
        float a1=(lane<17)?row[lane+32]:-1e30f;
        float m=fmaxf(a0,a1);
        #pragma unroll
        for(int o=16;o;o>>=1) m=fmaxf(m,__shfl_xor_sync(~0u,m,o));
        a0=__expf(a0-m);
        a1=(lane<17)?__expf(a1-m):0.f;
        float s=a0+a1;
        #pragma unroll
        for(int o=16;o;o>>=1) s+=__shfl_xor_sync(~0u,s,o);
        float inv=1.f/s;
        row[lane]=a0*inv; if(lane<17) row[lane+32]=a1*inv;
    }
    __syncthreads();
    // out = attn @ v -> (token, h*32+d) layout
    for(int idx=tid;idx<1568;idx+=256){
        int n=idx>>5, d=idx&31;
        float acc=0.f; const float* sr=A+n*50;
        #pragma unroll 7
        for(int m2=0;m2<49;m2++) acc+=sr[m2]*V[m2*33+d];
        g_ao[(size_t)(win*49+n)*512 + h*32 + d]=acc;
    }
}

// ---------- window reverse + roll(+3,+3) + residual + LN2 ----------
__global__ void __launch_bounds__(256) rev_ln2(const float* __restrict__ x,
    const float* __restrict__ w, const float* __restrict__ b)
{
    int t=blockIdx.x, tid=threadIdx.x;
    int bb=t/LTOK, rem=t-bb*LTOK;
    int hh=rem/112, ww=rem-112*hh;
    int hs=hh+109; if(hs>=112) hs-=112;
    int ws=ww+109; if(ws>=112) ws-=112;
    int win=bb*256 + (hs/7)*16 + (ws/7);
    int n=(hs%7)*7 + (ws%7);
    const float* pr=g_proj + (size_t)(win*49+n)*512;
    const float* xr=x + (size_t)t*512;
    float v0=xr[tid]+pr[tid], v1=xr[tid+256]+pr[tid+256];
    float mu,rs; ln_stats(v0,v1,mu,rs);
    float* o2=g_x2 + (size_t)t*512;
    float* ol=g_ln2 + (size_t)t*512;
    o2[tid]=v0; o2[tid+256]=v1;
    ol[tid]    =(v0-mu)*rs*w[tid]    +b[tid];
    ol[tid+256]=(v1-mu)*rs*w[tid+256]+b[tid+256];
}

// ---------- launch ----------
extern "C" void kernel_launch(void* const* d_in, const int* in_sizes, int n_in,
                              void* d_out, int out_size)
{
    const float* x    =(const float*)d_in[0];
    const float* x_ref=(const float*)d_in[1];
    const float* mask =(const float*)d_in[2];
    const float* n1w  =(const float*)d_in[3];
    const float* n1b  =(const float*)d_in[4];
    const float* qkvw =(const float*)d_in[5];
    const float* qkvb =(const float*)d_in[6];
    const float* dmu  =(const float*)d_in[7];
    const float* dls  =(const float*)d_in[8];
    const float* rpb  =(const float*)d_in[9];
    const float* rqw  =(const float*)d_in[10];
    const float* rqb  =(const float*)d_in[11];
    const float* cw   =(const float*)d_in[12];
    const float* cb   =(const float*)d_in[13];
    const float* pw   =(const float*)d_in[14];
    const float* pb   =(const float*)d_in[15];
    const float* n2w  =(const float*)d_in[16];
    const float* n2b  =(const float*)d_in[17];
    const float* f1w  =(const float*)d_in[18];
    const float* f1b  =(const float*)d_in[19];
    const float* f2w  =(const float*)d_in[20];
    const float* f2b  =(const float*)d_in[21];
    float* out=(float*)d_out;
    (void)in_sizes; (void)n_in; (void)out_size;

    float *p_xw, *p_qkv, *p_ao, *p_proj, *p_ln2, *p_fc1, *p_x2;
    cudaGetSymbolAddress((void**)&p_xw,  g_xw);
    cudaGetSymbolAddress((void**)&p_qkv, g_qkv);
    cudaGetSymbolAddress((void**)&p_ao,  g_ao);
    cudaGetSymbolAddress((void**)&p_proj,g_proj);
    cudaGetSymbolAddress((void**)&p_ln2, g_ln2);
    cudaGetSymbolAddress((void**)&p_fc1, g_fc1);
    cudaGetSymbolAddress((void**)&p_x2,  g_x2);

    ln1_shift<<<TTOK,256>>>(x, n1w, n1b);
    tgemm_nt<0><<<dim3(12,196),256>>>(p_xw, qkvw, qkvb, nullptr, p_qkv, 1536, 512);
    refqk<<<200,256>>>(x_ref, rqw, rqb, dmu, dls);
    ra_kernel<<<8192,256>>>();
    for(int it=0; it<3; it++){
        zero_stats<<<1,32>>>();
        conv3x3<<<dim3(6272,2),dim3(128,2)>>>(cw, cb);
        finalize_stats<<<1,32>>>();
        norm_gelu<<<dim3(1225,32),256>>>();
    }
    attn_kernel<<<8192,256>>>(mask, rpb);
    tgemm_nt<0><<<dim3(4,196),256>>>(p_ao, pw, pb, nullptr, p_proj, 512, 512);
    rev_ln2<<<TTOK,256>>>(x, n2w, n2b);
    tgemm_nt<1><<<dim3(16,196),256>>>(p_ln2, f1w, f1b, nullptr, p_fc1, 2048, 512);
    tgemm_nt<2><<<dim3(4,196),256>>>(p_fc1, f2w, f2b, p_x2, out, 512, 2048);
}

// round 12
// speedup vs baseline: 2.6515x; 1.0751x over previous
#include <cuda_runtime.h>
#include <math.h>

#define HEADS 16
#define HD    32
#define CDIM  512
#define NREF  100
#define LTOK  12544
#define TTOK  25088
#define RH    12544
#define RW    100
#define PLANE ((size_t)RH*RW)
#define EPSV  1e-5f
#define SCALEV 0.17677669529663687f

// ---------- scratch ----------
static __device__ float g_xw [(size_t)TTOK*CDIM];
static __device__ float g_qkv[(size_t)TTOK*3*CDIM];
static __device__ float g_refq[2*HEADS*NREF*HD];
static __device__ float g_refv[2*HEADS*NREF*HD];
static __device__ float g_ra [(size_t)32*PLANE];
static __device__ float g_u  [(size_t)32*PLANE];
static __device__ float g_ao [(size_t)TTOK*CDIM];
static __device__ float g_proj[(size_t)TTOK*CDIM];
static __device__ float g_x2 [(size_t)TTOK*CDIM];
static __device__ float g_ln2[(size_t)TTOK*CDIM];
static __device__ float g_fc1[(size_t)TTOK*4*CDIM];
static __device__ double g_ss[32], g_sq[32];
static __device__ float g_mu[32], g_rsd[32];

__device__ __forceinline__ float gelu_f(float x){
    return 0.5f*x*(1.f+erff(x*0.70710678118654752f));
}

__device__ __forceinline__ unsigned s2u(const void* p){
    return (unsigned)__cvta_generic_to_shared(p);
}
#define CP16(dst,src) asm volatile("cp.async.cg.shared.global [%0], [%1], 16;\n"::"r"(dst),"l"(src):"memory")
#define CPCOMMIT()    asm volatile("cp.async.commit_group;\n":::"memory")
#define CPWAIT(n)     asm volatile("cp.async.wait_group %0;\n"::"n"(n):"memory")

// block-wide LN stats for a 512-wide row held as (v0,v1) per thread (256 threads)
__device__ __forceinline__ void ln_stats(float v0, float v1, float& mu, float& rs){
    __shared__ float r1[8], r2[8];
    __shared__ float smu, srs;
    float s=v0+v1, q=v0*v0+v1*v1;
    #pragma unroll
    for(int o=16;o;o>>=1){ s+=__shfl_xor_sync(~0u,s,o); q+=__shfl_xor_sync(~0u,q,o); }
    int tid=threadIdx.x;
    if((tid&31)==0){ r1[tid>>5]=s; r2[tid>>5]=q; }
    __syncthreads();
    if(tid==0){
        float S=0.f,Q=0.f;
        #pragma unroll
        for(int i=0;i<8;i++){S+=r1[i];Q+=r2[i];}
        float m=S*(1.f/512.f);
        smu=m; srs=rsqrtf(Q*(1.f/512.f)-m*m+EPSV);
    }
    __syncthreads();
    mu=smu; rs=srs;
}

// ---------- LN1 + shift(-3,-3) + window partition -> g_xw ----------
__global__ void __launch_bounds__(256) ln1_shift(const float* __restrict__ x,
    const float* __restrict__ w, const float* __restrict__ b)
{
    int t=blockIdx.x, tid=threadIdx.x;
    int win=t/49, n=t-49*win;
    int bb=win>>8, wi=win&255;
    int r=n/7, c=n-7*r;
    int hs=(wi>>4)*7 + r + 3; if(hs>=112) hs-=112;
    int ws=(wi&15)*7 + c + 3; if(ws>=112) ws-=112;
    const float* xr = x + ((size_t)bb*LTOK + hs*112 + ws)*CDIM;
    float v0=xr[tid], v1=xr[tid+256];
    float mu,rs; ln_stats(v0,v1,mu,rs);
    float* o = g_xw + (size_t)t*CDIM;
    o[tid]      =(v0-mu)*rs*w[tid]      +b[tid];
    o[tid+256]  =(v1-mu)*rs*w[tid+256]  +b[tid+256];
}

// ---------- TF32 tensor-core NT GEMM, cp.async double-buffered ----------
// C[M,Nc]=A[M,K]@W[Nc,K]^T  EPI 0: +bias  1: gelu(+bias)  2: +bias+add
// fp32 fed raw into HMMA.TF32 (HW truncates mantissa)
template<int EPI>
__global__ void __launch_bounds__(256) tgemm_nt(const float* __restrict__ A,
    const float* __restrict__ W, const float* __restrict__ bias,
    const float* __restrict__ add, float* __restrict__ C, int Nc, int K)
{
    __shared__ float As[2][128][20];
    __shared__ float Bs[2][128][20];
    int tid=threadIdx.x;
    int wid=tid>>5, lane=tid&31;
    int wm=(wid&3)*32, wn=(wid>>2)*64;
    int gid=lane>>2, tg=lane&3;
    int bm=blockIdx.y*128, bn=blockIdx.x*128;
    int lrow=tid>>1, lcol=(tid&1)*8;
    const float* Ap=A+(size_t)(bm+lrow)*K+lcol;
    const float* Wp=W+(size_t)(bn+lrow)*K+lcol;
    unsigned sa0=s2u(&As[0][lrow][lcol]), sa1=s2u(&As[1][lrow][lcol]);
    unsigned sb0=s2u(&Bs[0][lrow][lcol]), sb1=s2u(&Bs[1][lrow][lcol]);

    float acc[2][8][4];
    #pragma unroll
    for(int f=0;f<2;f++)
        #pragma unroll
        for(int j=0;j<8;j++)
            #pragma unroll
            for(int q=0;q<4;q++) acc[f][j][q]=0.f;

    // prologue: stage 0
    CP16(sa0, Ap);    CP16(sa0+16, Ap+4);
    CP16(sb0, Wp);    CP16(sb0+16, Wp+4);
    CPCOMMIT();

    for(int k0=0;k0<K;k0+=16){
        int s=(k0>>4)&1;
        if(k0+16<K){
            unsigned da=s?sa0:sa1, db=s?sb0:sb1;
            CP16(da, Ap+k0+16); CP16(da+16, Ap+k0+20);
            CP16(db, Wp+k0+16); CP16(db+16, Wp+k0+20);
            CPCOMMIT();
            CPWAIT(1);
        } else {
            CPWAIT(0);
        }
        __syncthreads();
        #pragma unroll
        for(int kk=0;kk<16;kk+=8){
            unsigned af[2][4];
            #pragma unroll
            for(int f=0;f<2;f++){
                int m=wm+f*16+gid;
                af[f][0]=__float_as_uint(As[s][m  ][kk+tg  ]);
                af[f][1]=__float_as_uint(As[s][m+8][kk+tg  ]);
                af[f][2]=__float_as_uint(As[s][m  ][kk+tg+4]);
                af[f][3]=__float_as_uint(As[s][m+8][kk+tg+4]);
            }
            #pragma unroll
            for(int j=0;j<8;j++){
                int n=wn+j*8+gid;
                unsigned b0=__float_as_uint(Bs[s][n][kk+tg  ]);
                unsigned b1=__float_as_uint(Bs[s][n][kk+tg+4]);
                #pragma unroll
                for(int f=0;f<2;f++){
                    asm volatile(
                      "mma.sync.aligned.m16n8k8.row.col.f32.tf32.tf32.f32 "
                      "{%0,%1,%2,%3}, {%4,%5,%6,%7}, {%8,%9}, {%0,%1,%2,%3};\n"
                      : "+f"(acc[f][j][0]),"+f"(acc[f][j][1]),
                        "+f"(acc[f][j][2]),"+f"(acc[f][j][3])
                      : "r"(af[f][0]),"r"(af[f][1]),"r"(af[f][2]),"r"(af[f][3]),
                        "r"(b0),"r"(b1));
                }
            }
        }
        __syncthreads();
    }

    #pragma unroll
    for(int f=0;f<2;f++){
        int r0=bm+wm+f*16+gid;
        #pragma unroll
        for(int j=0;j<8;j++){
            int col=bn+wn+j*8+tg*2;
            float2 bv=*(const float2*)(bias+col);
            float2 v0, v1;
            v0.x=acc[f][j][0]+bv.x; v0.y=acc[f][j][1]+bv.y;
            v1.x=acc[f][j][2]+bv.x; v1.y=acc[f][j][3]+bv.y;
            if(EPI==1){
                v0.x=gelu_f(v0.x); v0.y=gelu_f(v0.y);
                v1.x=gelu_f(v1.x); v1.y=gelu_f(v1.y);
            }
            if(EPI==2){
                float2 e0=*(const float2*)(add+(size_t)r0*Nc+col);
                float2 e1=*(const float2*)(add+(size_t)(r0+8)*Nc+col);
                v0.x+=e0.x; v0.y+=e0.y; v1.x+=e1.x; v1.y+=e1.y;
            }
            *(float2*)(C+(size_t)r0*Nc+col)=v0;
            *(float2*)(C+(size_t)(r0+8)*Nc+col)=v1;
        }
    }
}

// ---------- ref tokens ----------
__global__ void __launch_bounds__(256) refqk(const float* __restrict__ xr,
    const float* __restrict__ Wt, const float* __restrict__ bias,
    const float* __restrict__ dmu, const float* __restrict__ dls)
{
    __shared__ __align__(16) float xs[512];
    int row=blockIdx.x, tid=threadIdx.x;
    int rb=row/100, r=row-100*rb;
    const float* src=xr+(size_t)row*512;
    xs[tid]=src[tid]; xs[tid+256]=src[tid+256];
    __syncthreads();
    const float4* x4=(const float4*)xs;
    for(int rep=0;rep<4;rep++){
        int col=tid+rep*256;
        const float4* w4=(const float4*)(Wt+(size_t)col*512);
        float acc=bias[col];
        #pragma unroll 8
        for(int k=0;k<128;k++){
            float4 a=x4[k], b=w4[k];
            acc+=a.x*b.x+a.y*b.y+a.z*b.z+a.w*b.w;
        }
        if(col<512){
            int h=col>>5, d=col&31;
            g_refq[(((size_t)rb*16+h)*100+r)*32+d]=dmu[col]+expf(dls[col])*acc;
        }else{
            int cc=col-512, h=cc>>5, d=cc&31;
            g_refv[(((size_t)rb*16+h)*100+r)*32+d]=acc;
        }
    }
}

// ---------- ra = q @ ref_q^T per (window, head) -> conv layout ----------
__global__ void __launch_bounds__(256) ra_kernel()
{
    __shared__ __align__(16) float qs[1568];
    __shared__ __align__(16) float rs[3600];   // 100 rows, stride 36 (float4-aligned)
    int bx=blockIdx.x, tid=threadIdx.x;
    int win=bx>>4, h=bx&15, rb=win>>8, winb=win&255;
    for(int i=tid;i<1568;i+=256){
        int n=i>>5, d=i&31;
        qs[i]=g_qkv[(size_t)(win*49+n)*1536 + h*32 + d];
    }
    const float* rq = g_refq + (size_t)(rb*16+h)*3200;
    for(int i=tid;i<3200;i+=256){
        int r=i>>5, d=i&31;
        rs[r*36+d]=rq[i];
    }
    __syncthreads();
    float* out = g_ra + ((size_t)(rb*16+h)*RH + winb*49)*100;
    for(int idx=tid;idx<4900;idx+=256){
        int n=idx/100, r=idx-100*n;
        const float4* q4=(const float4*)(qs+n*32);
        const float4* r4=(const float4*)(rs+r*36);
        float acc=0.f;
        #pragma unroll
        for(int k=0;k<8;k++){
            float4 a=q4[k], b=r4[k];
            acc+=a.x*b.x+a.y*b.y+a.z*b.z+a.w*b.w;
        }
        out[idx]=acc;
    }
}

// ---------- conv diffusion ----------
__global__ void zero_stats(){
    if(threadIdx.x<32){ g_ss[threadIdx.x]=0.0; g_sq[threadIdx.x]=0.0; }
}

__global__ void __launch_bounds__(256) conv3x3(const float* __restrict__ cw,
    const float* __restrict__ cb)
{
    __shared__ float s_in[16][4][102];
    __shared__ __align__(16) float s_w[2304];   // [(ci*9+tap)*16+co]
    __shared__ float red_s[8][16], red_q[8][16];
    int tid=threadIdx.y*128+threadIdx.x;
    int h0=blockIdx.x*2, nb=blockIdx.y;
    for(int i=tid;i<2304;i+=256){
        int ci=i/144, t2=i-144*ci, tap=t2>>4, co=t2&15;
        s_w[i]=cw[(co*16+ci)*9+tap];
    }
    for(int i=tid;i<6528;i+=256){
        int ci=i/408, t2=i-408*ci, rr=t2/102, cc=t2-102*rr;
        int gr=h0-1+rr, gc=cc-1;
        float v=0.f;
        if(gr>=0 && gr<RH && gc>=0 && gc<100)
            v=g_ra[((size_t)(nb*16+ci)*RH+gr)*100+gc];
        s_in[ci][rr][cc]=v;
    }
    __syncthreads();
    int w=threadIdx.x, y=threadIdx.y;
    bool act=(w<100);
    float acc[16];
    #pragma unroll
    for(int co=0;co<16;co++) acc[co]=cb[co];
    if(act){
        #pragma unroll 4
        for(int ci=0;ci<16;ci++){
            #pragma unroll
            for(int dr=0;dr<3;dr++){
                #pragma unroll
                for(int dc=0;dc<3;dc++){
                    float v=s_in[ci][y+dr][w+dc];
                    const float4* wp=(const float4*)&s_w[(ci*9+dr*3+dc)*16];
                    #pragma unroll
                    for(int q=0;q<4;q++){
                        float4 ww=wp[q];
                        acc[q*4+0]+=ww.x*v; acc[q*4+1]+=ww.y*v;
                        acc[q*4+2]+=ww.z*v; acc[q*4+3]+=ww.w*v;
                    }
                }
            }
        }
        int hh=h0+y;
        #pragma unroll
        for(int co=0;co<16;co++)
            g_u[((size_t)(nb*16+co)*RH+hh)*100+w]=acc[co];
    }
    int wp2=tid>>5, lane=tid&31;
    #pragma unroll
    for(int co=0;co<16;co++){
        float s=act?acc[co]:0.f;
        float q=s*s;
        #pragma unroll
        for(int o=16;o;o>>=1){ s+=__shfl_xor_sync(~0u,s,o); q+=__shfl_xor_sync(~0u,q,o); }
        if(lane==0){ red_s[wp2][co]=s; red_q[wp2][co]=q; }
    }
    __syncthreads();
    if(tid<16){
        float S=0.f,Q=0.f;
        #pragma unroll
        for(int i=0;i<8;i++){ S+=red_s[i][tid]; Q+=red_q[i][tid]; }
        atomicAdd(&g_ss[nb*16+tid],(double)S);
        atomicAdd(&g_sq[nb*16+tid],(double)Q);
    }
}

// per-plane stats -> float mu / rstd (fp64 confined to 32 threads)
__global__ void finalize_stats(){
    int p=threadIdx.x;
    if(p<32){
        double cnt=1254400.0;
        double mu=g_ss[p]/cnt;
        double var=g_sq[p]/cnt - mu*mu;
        g_mu[p]=(float)mu;
        g_rsd[p]=(float)rsqrt(var+1e-5);
    }
}

// pure fp32, float4-vectorized: g_ra += gelu((g_u - mu)*rstd)
__global__ void __launch_bounds__(256) norm_gelu()
{
    int p=blockIdx.y;
    float m=g_mu[p], rs=g_rsd[p];
    size_t base=(size_t)p*PLANE + (((size_t)blockIdx.x*256 + threadIdx.x)<<2);
    float4 u=*(const float4*)(g_u+base);
    float4 r=*(const float4*)(g_ra+base);
    r.x+=gelu_f((u.x-m)*rs);
    r.y+=gelu_f((u.y-m)*rs);
    r.z+=gelu_f((u.z-m)*rs);
    r.w+=gelu_f((u.w-m)*rs);
    *(float4*)(g_ra+base)=r;
}

// ---------- fused attention per (window, head) ----------
__global__ void __launch_bounds__(256) attn_kernel(const float* __restrict__ mask,
    const float* __restrict__ rpb)
{
    __shared__ float A[4900];   // ra (49x100) -> scores (49 rows, stride 50)
    __shared__ float B[3200];   // refv (stride 32) -> k (stride 33)
    __shared__ float Q[1568];   // q_new (stride 32)
    __shared__ float V[1617];   // v (stride 33)
    int bx=blockIdx.x, tid=threadIdx.x;
    int win=bx>>4, h=bx&15, rb=win>>8, winb=win&255;
    int plane=rb*16+h;
    const float* raP=g_ra + ((size_t)plane*RH + winb*49)*100;
    for(int i=tid;i<4900;i+=256) A[i]=raP[i];
    const float* rvP=g_refv + (size_t)plane*3200;
    for(int i=tid;i<3200;i+=256) B[i]=rvP[i];
    for(int i=tid;i<1568;i+=256){
        int n=i>>5, d=i&31;
        V[n*33+d]=g_qkv[(size_t)(win*49+n)*1536 + 1024 + h*32 + d];
    }
    __syncthreads();
    int wp=tid>>5, lane=tid&31;
    // softmax over 100 per row
    for(int n=wp;n<49;n+=8){
        float* row=A+n*100;
        float e0=row[lane], e1=row[lane+32], e2=row[lane+64];
        float e3=(lane<4)?row[lane+96]:-1e30f;
        float m=fmaxf(fmaxf(e0,e1),fmaxf(e2,e3));
        #pragma unroll
        for(int o=16;o;o>>=1) m=fmaxf(m,__shfl_xor_sync(~0u,m,o));
        e0=__expf(e0-m); e1=__expf(e1-m); e2=__expf(e2-m);
        e3=(lane<4)?__expf(e3-m):0.f;
        float s=e0+e1+e2+e3;
        #pragma unroll
        for(int o=16;o;o>>=1) s+=__shfl_xor_sync(~0u,s,o);
        float inv=1.f/s;
        row[lane]=e0*inv; row[lane+32]=e1*inv; row[lane+64]=e2*inv;
        if(lane<4) row[lane+96]=e3*inv;
    }
    __syncthreads();
    // q_new = ra @ refv * SCALE
    for(int idx=tid;idx<1568;idx+=256){
        int n=idx>>5, d=idx&31;
        float acc=0.f; const float* ar=A+n*100;
        #pragma unroll 4
        for(int r=0;r<100;r++) acc+=ar[r]*B[r*32+d];
        Q[idx]=acc*SCALEV;
    }
    __syncthreads();
    // load k into B (stride 33)
    for(int i=tid;i<1568;i+=256){
        int n=i>>5, d=i&31;
        B[n*33+d]=g_qkv[(size_t)(win*49+n)*1536 + 512 + h*32 + d];
    }
    __syncthreads();
    // scores = q_new @ k^T + rpb + mask  (into A, stride 50)
    const float* mrow=mask + (size_t)winb*2401;
    for(int idx=tid;idx<2401;idx+=256){
        int n=idx/49, m2=idx-49*n;
        float acc=0.f; const float* qr=Q+n*32; const float* kr=B+m2*33;
        #pragma unroll
        for(int k=0;k<32;k++) acc+=qr[k]*kr[k];
        int rpi=(n/7 - m2/7 + 6)*13 + (n%7 - m2%7 + 6);
        acc += rpb[rpi*16+h] + mrow[idx];
        A[n*50+m2]=acc;
    }
    __syncthreads();
    // softmax over 49 per row
    for(int n=wp;n<49;n+=8){
        float* row=A+n*50;
        float a0=row[lane];
        float a1=(lane<17)?row[lane+32]:-1e30f;
        float m=fmaxf(a0,a1);
        #pragma unroll
        for(int o=16;o;o>>=1) m=fmaxf(m,__shfl_xor_sync(~0u,m,o));
        a0=__expf(a0-m);
        a1=(lane<17)?__expf(a1-m):0.f;
        float s=a0+a1;
        #pragma unroll
        for(int o=16;o;o>>=1) s+=__shfl_xor_sync(~0u,s,o);
        float inv=1.f/s;
        row[lane]=a0*inv; if(lane<17) row[lane+32]=a1*inv;
    }
    __syncthreads();
    // out = attn @ v -> (token, h*32+d) layout
    for(int idx=tid;idx<1568;idx+=256){
        int n=idx>>5, d=idx&31;
        float acc=0.f; const float* sr=A+n*50;
        #pragma unroll 7
        for(int m2=0;m2<49;m2++) acc+=sr[m2]*V[m2*33+d];
        g_ao[(size_t)(win*49+n)*512 + h*32 + d]=acc;
    }
}

// ---------- window reverse + roll(+3,+3) + residual + LN2 ----------
__global__ void __launch_bounds__(256) rev_ln2(const float* __restrict__ x,
    const float* __restrict__ w, const float* __restrict__ b)
{
    int t=blockIdx.x, tid=threadIdx.x;
    int bb=t/LTOK, rem=t-bb*LTOK;
    int hh=rem/112, ww=rem-112*hh;
    int hs=hh+109; if(hs>=112) hs-=112;
    int ws=ww+109; if(ws>=112) ws-=112;
    int win=bb*256 + (hs/7)*16 + (ws/7);
    int n=(hs%7)*7 + (ws%7);
    const float* pr=g_proj + (size_t)(win*49+n)*512;
    const float* xr=x + (size_t)t*512;
    float v0=xr[tid]+pr[tid], v1=xr[tid+256]+pr[tid+256];
    float mu,rs; ln_stats(v0,v1,mu,rs);
    float* o2=g_x2 + (size_t)t*512;
    float* ol=g_ln2 + (size_t)t*512;
    o2[tid]=v0; o2[tid+256]=v1;
    ol[tid]    =(v0-mu)*rs*w[tid]    +b[tid];
    ol[tid+256]=(v1-mu)*rs*w[tid+256]+b[tid+256];
}

// ---------- launch ----------
extern "C" void kernel_launch(void* const* d_in, const int* in_sizes, int n_in,
                              void* d_out, int out_size)
{
    const float* x    =(const float*)d_in[0];
    const float* x_ref=(const float*)d_in[1];
    const float* mask =(const float*)d_in[2];
    const float* n1w  =(const float*)d_in[3];
    const float* n1b  =(const float*)d_in[4];
    const float* qkvw =(const float*)d_in[5];
    const float* qkvb =(const float*)d_in[6];
    const float* dmu  =(const float*)d_in[7];
    const float* dls  =(const float*)d_in[8];
    const float* rpb  =(const float*)d_in[9];
    const float* rqw  =(const float*)d_in[10];
    const float* rqb  =(const float*)d_in[11];
    const float* cw   =(const float*)d_in[12];
    const float* cb   =(const float*)d_in[13];
    const float* pw   =(const float*)d_in[14];
    const float* pb   =(const float*)d_in[15];
    const float* n2w  =(const float*)d_in[16];
    const float* n2b  =(const float*)d_in[17];
    const float* f1w  =(const float*)d_in[18];
    const float* f1b  =(const float*)d_in[19];
    const float* f2w  =(const float*)d_in[20];
    const float* f2b  =(const float*)d_in[21];
    float* out=(float*)d_out;
    (void)in_sizes; (void)n_in; (void)out_size;

    float *p_xw, *p_qkv, *p_ao, *p_proj, *p_ln2, *p_fc1, *p_x2;
    cudaGetSymbolAddress((void**)&p_xw,  g_xw);
    cudaGetSymbolAddress((void**)&p_qkv, g_qkv);
    cudaGetSymbolAddress((void**)&p_ao,  g_ao);
    cudaGetSymbolAddress((void**)&p_proj,g_proj);
    cudaGetSymbolAddress((void**)&p_ln2, g_ln2);
    cudaGetSymbolAddress((void**)&p_fc1, g_fc1);
    cudaGetSymbolAddress((void**)&p_x2,  g_x2);

    ln1_shift<<<TTOK,256>>>(x, n1w, n1b);
    tgemm_nt<0><<<dim3(12,196),256>>>(p_xw, qkvw, qkvb, nullptr, p_qkv, 1536, 512);
    refqk<<<200,256>>>(x_ref, rqw, rqb, dmu, dls);
    ra_kernel<<<8192,256>>>();
    for(int it=0; it<3; it++){
        zero_stats<<<1,32>>>();
        conv3x3<<<dim3(6272,2),dim3(128,2)>>>(cw, cb);
        finalize_stats<<<1,32>>>();
        norm_gelu<<<dim3(1225,32),256>>>();
    }
    attn_kernel<<<8192,256>>>(mask, rpb);
    tgemm_nt<0><<<dim3(4,196),256>>>(p_ao, pw, pb, nullptr, p_proj, 512, 512);
    rev_ln2<<<TTOK,256>>>(x, n2w, n2b);
    tgemm_nt<1><<<dim3(16,196),256>>>(p_ln2, f1w, f1b, nullptr, p_fc1, 2048, 512);
    tgemm_nt<2><<<dim3(4,196),256>>>(p_fc1, f2w, f2b, p_x2, out, 512, 2048);
}

// round 13
// speedup vs baseline: 3.0204x; 1.1391x over previous
#include <cuda_runtime.h>
#include <math.h>

#define HEADS 16
#define HD    32
#define CDIM  512
#define NREF  100
#define LTOK  12544
#define TTOK  25088
#define RH    12544
#define RW    100
#define PLANE ((size_t)RH*RW)
#define EPSV  1e-5f
#define SCALEV 0.17677669529663687f

// ---------- scratch ----------
static __device__ float g_xw [(size_t)TTOK*CDIM];
static __device__ float g_qkv[(size_t)TTOK*3*CDIM];
static __device__ float g_refq[2*HEADS*NREF*HD];
static __device__ float g_refv[2*HEADS*NREF*HD];
static __device__ float g_ra [(size_t)32*PLANE];
static __device__ float g_u  [(size_t)32*PLANE];
static __device__ float g_ao [(size_t)TTOK*CDIM];
static __device__ float g_proj[(size_t)TTOK*CDIM];
static __device__ float g_x2 [(size_t)TTOK*CDIM];
static __device__ float g_ln2[(size_t)TTOK*CDIM];
static __device__ float g_fc1[(size_t)TTOK*4*CDIM];
static __device__ double g_ss[32], g_sq[32];
static __device__ float g_mu[32], g_rsd[32];

__device__ __forceinline__ float gelu_f(float x){
    return 0.5f*x*(1.f+erff(x*0.70710678118654752f));
}

__device__ __forceinline__ unsigned s2u(const void* p){
    return (unsigned)__cvta_generic_to_shared(p);
}
#define CP16(dst,src) asm volatile("cp.async.cg.shared.global [%0], [%1], 16;\n"::"r"(dst),"l"(src):"memory")
#define CPCOMMIT()    asm volatile("cp.async.commit_group;\n":::"memory")
#define CPWAIT(n)     asm volatile("cp.async.wait_group %0;\n"::"n"(n):"memory")

// block-wide LN stats for a 512-wide row held as (v0,v1) per thread (256 threads)
__device__ __forceinline__ void ln_stats(float v0, float v1, float& mu, float& rs){
    __shared__ float r1[8], r2[8];
    __shared__ float smu, srs;
    float s=v0+v1, q=v0*v0+v1*v1;
    #pragma unroll
    for(int o=16;o;o>>=1){ s+=__shfl_xor_sync(~0u,s,o); q+=__shfl_xor_sync(~0u,q,o); }
    int tid=threadIdx.x;
    if((tid&31)==0){ r1[tid>>5]=s; r2[tid>>5]=q; }
    __syncthreads();
    if(tid==0){
        float S=0.f,Q=0.f;
        #pragma unroll
        for(int i=0;i<8;i++){S+=r1[i];Q+=r2[i];}
        float m=S*(1.f/512.f);
        smu=m; srs=rsqrtf(Q*(1.f/512.f)-m*m+EPSV);
    }
    __syncthreads();
    mu=smu; rs=srs;
}

// ---------- LN1 + shift(-3,-3) + window partition -> g_xw ----------
__global__ void __launch_bounds__(256) ln1_shift(const float* __restrict__ x,
    const float* __restrict__ w, const float* __restrict__ b)
{
    int t=blockIdx.x, tid=threadIdx.x;
    int win=t/49, n=t-49*win;
    int bb=win>>8, wi=win&255;
    int r=n/7, c=n-7*r;
    int hs=(wi>>4)*7 + r + 3; if(hs>=112) hs-=112;
    int ws=(wi&15)*7 + c + 3; if(ws>=112) ws-=112;
    const float* xr = x + ((size_t)bb*LTOK + hs*112 + ws)*CDIM;
    float v0=xr[tid], v1=xr[tid+256];
    float mu,rs; ln_stats(v0,v1,mu,rs);
    float* o = g_xw + (size_t)t*CDIM;
    o[tid]      =(v0-mu)*rs*w[tid]      +b[tid];
    o[tid+256]  =(v1-mu)*rs*w[tid+256]  +b[tid+256];
}

// ---------- TF32 tensor-core NT GEMM, cp.async double-buffered ----------
// C[M,Nc]=A[M,K]@W[Nc,K]^T  EPI 0: +bias  1: gelu(+bias)  2: +bias+add
template<int EPI>
__global__ void __launch_bounds__(256) tgemm_nt(const float* __restrict__ A,
    const float* __restrict__ W, const float* __restrict__ bias,
    const float* __restrict__ add, float* __restrict__ C, int Nc, int K)
{
    __shared__ float As[2][128][20];
    __shared__ float Bs[2][128][20];
    int tid=threadIdx.x;
    int wid=tid>>5, lane=tid&31;
    int wm=(wid&3)*32, wn=(wid>>2)*64;
    int gid=lane>>2, tg=lane&3;
    int bm=blockIdx.y*128, bn=blockIdx.x*128;
    int lrow=tid>>1, lcol=(tid&1)*8;
    const float* Ap=A+(size_t)(bm+lrow)*K+lcol;
    const float* Wp=W+(size_t)(bn+lrow)*K+lcol;
    unsigned sa0=s2u(&As[0][lrow][lcol]), sa1=s2u(&As[1][lrow][lcol]);
    unsigned sb0=s2u(&Bs[0][lrow][lcol]), sb1=s2u(&Bs[1][lrow][lcol]);

    float acc[2][8][4];
    #pragma unroll
    for(int f=0;f<2;f++)
        #pragma unroll
        for(int j=0;j<8;j++)
            #pragma unroll
            for(int q=0;q<4;q++) acc[f][j][q]=0.f;

    CP16(sa0, Ap);    CP16(sa0+16, Ap+4);
    CP16(sb0, Wp);    CP16(sb0+16, Wp+4);
    CPCOMMIT();

    for(int k0=0;k0<K;k0+=16){
        int s=(k0>>4)&1;
        if(k0+16<K){
            unsigned da=s?sa0:sa1, db=s?sb0:sb1;
            CP16(da, Ap+k0+16); CP16(da+16, Ap+k0+20);
            CP16(db, Wp+k0+16); CP16(db+16, Wp+k0+20);
            CPCOMMIT();
            CPWAIT(1);
        } else {
            CPWAIT(0);
        }
        __syncthreads();
        #pragma unroll
        for(int kk=0;kk<16;kk+=8){
            unsigned af[2][4];
            #pragma unroll
            for(int f=0;f<2;f++){
                int m=wm+f*16+gid;
                af[f][0]=__float_as_uint(As[s][m  ][kk+tg  ]);
                af[f][1]=__float_as_uint(As[s][m+8][kk+tg  ]);
                af[f][2]=__float_as_uint(As[s][m  ][kk+tg+4]);
                af[f][3]=__float_as_uint(As[s][m+8][kk+tg+4]);
            }
            #pragma unroll
            for(int j=0;j<8;j++){
                int n=wn+j*8+gid;
                unsigned b0=__float_as_uint(Bs[s][n][kk+tg  ]);
                unsigned b1=__float_as_uint(Bs[s][n][kk+tg+4]);
                #pragma unroll
                for(int f=0;f<2;f++){
                    asm volatile(
                      "mma.sync.aligned.m16n8k8.row.col.f32.tf32.tf32.f32 "
                      "{%0,%1,%2,%3}, {%4,%5,%6,%7}, {%8,%9}, {%0,%1,%2,%3};\n"
                      : "+f"(acc[f][j][0]),"+f"(acc[f][j][1]),
                        "+f"(acc[f][j][2]),"+f"(acc[f][j][3])
                      : "r"(af[f][0]),"r"(af[f][1]),"r"(af[f][2]),"r"(af[f][3]),
                        "r"(b0),"r"(b1));
                }
            }
        }
        __syncthreads();
    }

    #pragma unroll
    for(int f=0;f<2;f++){
        int r0=bm+wm+f*16+gid;
        #pragma unroll
        for(int j=0;j<8;j++){
            int col=bn+wn+j*8+tg*2;
            float2 bv=*(const float2*)(bias+col);
            float2 v0, v1;
            v0.x=acc[f][j][0]+bv.x; v0.y=acc[f][j][1]+bv.y;
            v1.x=acc[f][j][2]+bv.x; v1.y=acc[f][j][3]+bv.y;
            if(EPI==1){
                v0.x=gelu_f(v0.x); v0.y=gelu_f(v0.y);
                v1.x=gelu_f(v1.x); v1.y=gelu_f(v1.y);
            }
            if(EPI==2){
                float2 e0=*(const float2*)(add+(size_t)r0*Nc+col);
                float2 e1=*(const float2*)(add+(size_t)(r0+8)*Nc+col);
                v0.x+=e0.x; v0.y+=e0.y; v1.x+=e1.x; v1.y+=e1.y;
            }
            *(float2*)(C+(size_t)r0*Nc+col)=v0;
            *(float2*)(C+(size_t)(r0+8)*Nc+col)=v1;
        }
    }
}

// ---------- ref tokens ----------
__global__ void __launch_bounds__(256) refqk(const float* __restrict__ xr,
    const float* __restrict__ Wt, const float* __restrict__ bias,
    const float* __restrict__ dmu, const float* __restrict__ dls)
{
    __shared__ __align__(16) float xs[512];
    int row=blockIdx.x, tid=threadIdx.x;
    int rb=row/100, r=row-100*rb;
    const float* src=xr+(size_t)row*512;
    xs[tid]=src[tid]; xs[tid+256]=src[tid+256];
    __syncthreads();
    const float4* x4=(const float4*)xs;
    for(int rep=0;rep<4;rep++){
        int col=tid+rep*256;
        const float4* w4=(const float4*)(Wt+(size_t)col*512);
        float acc=bias[col];
        #pragma unroll 8
        for(int k=0;k<128;k++){
            float4 a=x4[k], b=w4[k];
            acc+=a.x*b.x+a.y*b.y+a.z*b.z+a.w*b.w;
        }
        if(col<512){
            int h=col>>5, d=col&31;
            g_refq[(((size_t)rb*16+h)*100+r)*32+d]=dmu[col]+expf(dls[col])*acc;
        }else{
            int cc=col-512, h=cc>>5, d=cc&31;
            g_refv[(((size_t)rb*16+h)*100+r)*32+d]=acc;
        }
    }
}

// ---------- ra = q @ ref_q^T per (window, head) -> conv layout ----------
__global__ void __launch_bounds__(256) ra_kernel()
{
    __shared__ __align__(16) float qs[1568];
    __shared__ __align__(16) float rs[3600];   // 100 rows, stride 36
    int bx=blockIdx.x, tid=threadIdx.x;
    int win=bx>>4, h=bx&15, rb=win>>8, winb=win&255;
    for(int i=tid;i<1568;i+=256){
        int n=i>>5, d=i&31;
        qs[i]=g_qkv[(size_t)(win*49+n)*1536 + h*32 + d];
    }
    const float* rq = g_refq + (size_t)(rb*16+h)*3200;
    for(int i=tid;i<3200;i+=256){
        int r=i>>5, d=i&31;
        rs[r*36+d]=rq[i];
    }
    __syncthreads();
    float* out = g_ra + ((size_t)(rb*16+h)*RH + winb*49)*100;
    for(int idx=tid;idx<4900;idx+=256){
        int n=idx/100, r=idx-100*n;
        const float4* q4=(const float4*)(qs+n*32);
        const float4* r4=(const float4*)(rs+r*36);
        float acc=0.f;
        #pragma unroll
        for(int k=0;k<8;k++){
            float4 a=q4[k], b=r4[k];
            acc+=a.x*b.x+a.y*b.y+a.z*b.z+a.w*b.w;
        }
        out[idx]=acc;
    }
}

// ---------- conv diffusion ----------
__global__ void zero_stats(){
    if(threadIdx.x<32){ g_ss[threadIdx.x]=0.0; g_sq[threadIdx.x]=0.0; }
}

// 3x3x16->16 conv, packed f32x2 FMA, 2 rows per thread (block = 4 rows)
__global__ void __launch_bounds__(256) conv3x3(const float* __restrict__ cw,
    const float* __restrict__ cb)
{
    __shared__ float s_in[16][6][102];
    __shared__ __align__(16) float s_w[2304];   // [(ci*9+tap)*16+co]
    __shared__ float red_s[8][16], red_q[8][16];
    int tid=threadIdx.y*128+threadIdx.x;
    int h0=blockIdx.x*4, nb=blockIdx.y;
    for(int i=tid;i<2304;i+=256){
        int ci=i/144, t2=i-144*ci, tap=t2>>4, co=t2&15;
        s_w[i]=cw[(co*16+ci)*9+tap];
    }
    for(int i=tid;i<9792;i+=256){
        int ci=i/612, t2=i-612*ci, rr=t2/102, cc=t2-102*rr;
        int gr=h0-1+rr, gc=cc-1;
        float v=0.f;
        if(gr>=0 && gr<RH && gc>=0 && gc<100)
            v=g_ra[((size_t)(nb*16+ci)*RH+gr)*100+gc];
        s_in[ci][rr][cc]=v;
    }
    __syncthreads();
    int w=threadIdx.x, y=threadIdx.y;
    bool act=(w<100);
    unsigned long long acc[2][8];
    #pragma unroll
    for(int q=0;q<8;q++){
        unsigned long long p;
        asm("mov.b64 %0,{%1,%2};":"=l"(p):"f"(cb[q*2]),"f"(cb[q*2+1]));
        acc[0][q]=p; acc[1][q]=p;
    }
    if(act){
        #pragma unroll 4
        for(int ci=0;ci<16;ci++){
            #pragma unroll
            for(int dr=0;dr<3;dr++){
                #pragma unroll
                for(int dc=0;dc<3;dc++){
                    float v0=s_in[ci][y*2+dr  ][w+dc];
                    float v1=s_in[ci][y*2+dr+1][w+dc];
                    unsigned long long p0,p1;
                    asm("mov.b64 %0,{%1,%1};":"=l"(p0):"f"(v0));
                    asm("mov.b64 %0,{%1,%1};":"=l"(p1):"f"(v1));
                    const ulonglong2* wp=(const ulonglong2*)&s_w[(ci*9+dr*3+dc)*16];
                    #pragma unroll
                    for(int q2=0;q2<4;q2++){
                        ulonglong2 ww=wp[q2];
                        asm("fma.rn.f32x2 %0,%1,%2,%0;":"+l"(acc[0][q2*2  ]):"l"(ww.x),"l"(p0));
                        asm("fma.rn.f32x2 %0,%1,%2,%0;":"+l"(acc[0][q2*2+1]):"l"(ww.y),"l"(p0));
                        asm("fma.rn.f32x2 %0,%1,%2,%0;":"+l"(acc[1][q2*2  ]):"l"(ww.x),"l"(p1));
                        asm("fma.rn.f32x2 %0,%1,%2,%0;":"+l"(acc[1][q2*2+1]):"l"(ww.y),"l"(p1));
                    }
                }
            }
        }
    }
    float a[2][16];
    #pragma unroll
    for(int r=0;r<2;r++)
        #pragma unroll
        for(int q=0;q<8;q++){
            float lo,hi;
            asm("mov.b64 {%0,%1},%2;":"=f"(lo),"=f"(hi):"l"(acc[r][q]));
            a[r][q*2]=lo; a[r][q*2+1]=hi;
        }
    if(act){
        int hh=h0+y*2;
        #pragma unroll
        for(int r=0;r<2;r++)
            #pragma unroll
            for(int co=0;co<16;co++)
                g_u[((size_t)(nb*16+co)*RH+hh+r)*100+w]=a[r][co];
    }
    int wp2=tid>>5, lane=tid&31;
    #pragma unroll
    for(int co=0;co<16;co++){
        float s=act?(a[0][co]+a[1][co]):0.f;
        float q=act?(a[0][co]*a[0][co]+a[1][co]*a[1][co]):0.f;
        #pragma unroll
        for(int o=16;o;o>>=1){ s+=__shfl_xor_sync(~0u,s,o); q+=__shfl_xor_sync(~0u,q,o); }
        if(lane==0){ red_s[wp2][co]=s; red_q[wp2][co]=q; }
    }
    __syncthreads();
    if(tid<16){
        float S=0.f,Q=0.f;
        #pragma unroll
        for(int i=0;i<8;i++){ S+=red_s[i][tid]; Q+=red_q[i][tid]; }
        atomicAdd(&g_ss[nb*16+tid],(double)S);
        atomicAdd(&g_sq[nb*16+tid],(double)Q);
    }
}

// per-plane stats -> float mu / rstd (fp64 confined to 32 threads)
__global__ void finalize_stats(){
    int p=threadIdx.x;
    if(p<32){
        double cnt=1254400.0;
        double mu=g_ss[p]/cnt;
        double var=g_sq[p]/cnt - mu*mu;
        g_mu[p]=(float)mu;
        g_rsd[p]=(float)rsqrt(var+1e-5);
    }
}

// pure fp32, float4-vectorized: g_ra += gelu((g_u - mu)*rstd)
__global__ void __launch_bounds__(256) norm_gelu()
{
    int p=blockIdx.y;
    float m=g_mu[p], rs=g_rsd[p];
    size_t base=(size_t)p*PLANE + (((size_t)blockIdx.x*256 + threadIdx.x)<<2);
    float4 u=*(const float4*)(g_u+base);
    float4 r=*(const float4*)(g_ra+base);
    r.x+=gelu_f((u.x-m)*rs);
    r.y+=gelu_f((u.y-m)*rs);
    r.z+=gelu_f((u.z-m)*rs);
    r.w+=gelu_f((u.w-m)*rs);
    *(float4*)(g_ra+base)=r;
}

// ---------- fused attention per (window, head) ----------
__global__ void __launch_bounds__(256) attn_kernel(const float* __restrict__ mask,
    const float* __restrict__ rpb)
{
    __shared__ float A[4900];   // ra (49x100) -> scores (49 rows, stride 50)
    __shared__ float B[3200];   // refv (stride 32) -> k (stride 33)
    __shared__ float Q[1568];   // q_new (stride 32)
    __shared__ float V[1617];   // v (stride 33)
    int bx=blockIdx.x, tid=threadIdx.x;
    int win=bx>>4, h=bx&15, rb=win>>8, winb=win&255;
    int plane=rb*16+h;
    const float* raP=g_ra + ((size_t)plane*RH + winb*49)*100;
    for(int i=tid;i<4900;i+=256) A[i]=raP[i];
    const float* rvP=g_refv + (size_t)plane*3200;
    for(int i=tid;i<3200;i+=256) B[i]=rvP[i];
    for(int i=tid;i<1568;i+=256){
        int n=i>>5, d=i&31;
        V[n*33+d]=g_qkv[(size_t)(win*49+n)*1536 + 1024 + h*32 + d];
    }
    __syncthreads();
    int wp=tid>>5, lane=tid&31;
    for(int n=wp;n<49;n+=8){
        float* row=A+n*100;
        float e0=row[lane], e1=row[lane+32], e2=row[lane+64];
        float e3=(lane<4)?row[lane+96]:-1e30f;
        float m=fmaxf(fmaxf(e0,e1),fmaxf(e2,e3));
        #pragma unroll
        for(int o=16;o;o>>=1) m=fmaxf(m,__shfl_xor_sync(~0u,m,o));
        e0=__expf(e0-m); e1=__expf(e1-m); e2=__expf(e2-m);
        e3=(lane<4)?__expf(e3-m):0.f;
        float s=e0+e1+e2+e3;
        #pragma unroll
        for(int o=16;o;o>>=1) s+=__shfl_xor_sync(~0u,s,o);
        float inv=1.f/s;
        row[lane]=e0*inv; row[lane+32]=e1*inv; row[lane+64]=e2*inv;
        if(lane<4) row[lane+96]=e3*inv;
    }
    __syncthreads();
    for(int idx=tid;idx<1568;idx+=256){
        int n=idx>>5, d=idx&31;
        float acc=0.f; const float* ar=A+n*100;
        #pragma unroll 4
        for(int r=0;r<100;r++) acc+=ar[r]*B[r*32+d];
        Q[idx]=acc*SCALEV;
    }
    __syncthreads();
    for(int i=tid;i<1568;i+=256){
        int n=i>>5, d=i&31;
        B[n*33+d]=g_qkv[(size_t)(win*49+n)*1536 + 512 + h*32 + d];
    }
    __syncthreads();
    const float* mrow=mask + (size_t)winb*2401;
    for(int idx=tid;idx<2401;idx+=256){
        int n=idx/49, m2=idx-49*n;
        float acc=0.f; const float* qr=Q+n*32; const float* kr=B+m2*33;
        #pragma unroll
        for(int k=0;k<32;k++) acc+=qr[k]*kr[k];
        int rpi=(n/7 - m2/7 + 6)*13 + (n%7 - m2%7 + 6);
        acc += rpb[rpi*16+h] + mrow[idx];
        A[n*50+m2]=acc;
    }
    __syncthreads();
    for(int n=wp;n<49;n+=8){
        float* row=A+n*50;
        float a0=row[lane];
        float a1=(lane<17)?row[lane+32]:-1e30f;
        float m=fmaxf(a0,a1);
        #pragma unroll
        for(int o=16;o;o>>=1) m=fmaxf(m,__shfl_xor_sync(~0u,m,o));
        a0=__expf(a0-m);
        a1=(lane<17)?__expf(a1-m):0.f;
        float s=a0+a1;
        #pragma unroll
        for(int o=16;o;o>>=1) s+=__shfl_xor_sync(~0u,s,o);
        float inv=1.f/s;
        row[lane]=a0*inv; if(lane<17) row[lane+32]=a1*inv;
    }
    __syncthreads();
    for(int idx=tid;idx<1568;idx+=256){
        int n=idx>>5, d=idx&31;
        float acc=0.f; const float* sr=A+n*50;
        #pragma unroll 7
        for(int m2=0;m2<49;m2++) acc+=sr[m2]*V[m2*33+d];
        g_ao[(size_t)(win*49+n)*512 + h*32 + d]=acc;
    }
}

// ---------- window reverse + roll(+3,+3) + residual + LN2 ----------
__global__ void __launch_bounds__(256) rev_ln2(const float* __restrict__ x,
    const float* __restrict__ w, const float* __restrict__ b)
{
    int t=blockIdx.x, tid=threadIdx.x;
    int bb=t/LTOK, rem=t-bb*LTOK;
    int hh=rem/112, ww=rem-112*hh;
    int hs=hh+109; if(hs>=112) hs-=112;
    int ws=ww+109; if(ws>=112) ws-=112;
    int win=bb*256 + (hs/7)*16 + (ws/7);
    int n=(hs%7)*7 + (ws%7);
    const float* pr=g_proj + (size_t)(win*49+n)*512;
    const float* xr=x + (size_t)t*512;
    float v0=xr[tid]+pr[tid], v1=xr[tid+256]+pr[tid+256];
    float mu,rs; ln_stats(v0,v1,mu,rs);
    float* o2=g_x2 + (size_t)t*512;
    float* ol=g_ln2 + (size_t)t*512;
    o2[tid]=v0; o2[tid+256]=v1;
    ol[tid]    =(v0-mu)*rs*w[tid]    +b[tid];
    ol[tid+256]=(v1-mu)*rs*w[tid+256]+b[tid+256];
}

// ---------- launch ----------
extern "C" void kernel_launch(void* const* d_in, const int* in_sizes, int n_in,
                              void* d_out, int out_size)
{
    const float* x    =(const float*)d_in[0];
    const float* x_ref=(const float*)d_in[1];
    const float* mask =(const float*)d_in[2];
    const float* n1w  =(const float*)d_in[3];
    const float* n1b  =(const float*)d_in[4];
    const float* qkvw =(const float*)d_in[5];
    const float* qkvb =(const float*)d_in[6];
    const float* dmu  =(const float*)d_in[7];
    const float* dls  =(const float*)d_in[8];
    const float* rpb  =(const float*)d_in[9];
    const float* rqw  =(const float*)d_in[10];
    const float* rqb  =(const float*)d_in[11];
    const float* cw   =(const float*)d_in[12];
    const float* cb   =(const float*)d_in[13];
    const float* pw   =(const float*)d_in[14];
    const float* pb   =(const float*)d_in[15];
    const float* n2w  =(const float*)d_in[16];
    const float* n2b  =(const float*)d_in[17];
    const float* f1w  =(const float*)d_in[18];
    const float* f1b  =(const float*)d_in[19];
    const float* f2w  =(const float*)d_in[20];
    const float* f2b  =(const float*)d_in[21];
    float* out=(float*)d_out;
    (void)in_sizes; (void)n_in; (void)out_size;

    float *p_xw, *p_qkv, *p_ao, *p_proj, *p_ln2, *p_fc1, *p_x2;
    cudaGetSymbolAddress((void**)&p_xw,  g_xw);
    cudaGetSymbolAddress((void**)&p_qkv, g_qkv);
    cudaGetSymbolAddress((void**)&p_ao,  g_ao);
    cudaGetSymbolAddress((void**)&p_proj,g_proj);
    cudaGetSymbolAddress((void**)&p_ln2, g_ln2);
    cudaGetSymbolAddress((void**)&p_fc1, g_fc1);
    cudaGetSymbolAddress((void**)&p_x2,  g_x2);

    ln1_shift<<<TTOK,256>>>(x, n1w, n1b);
    tgemm_nt<0><<<dim3(12,196),256>>>(p_xw, qkvw, qkvb, nullptr, p_qkv, 1536, 512);
    refqk<<<200,256>>>(x_ref, rqw, rqb, dmu, dls);
    ra_kernel<<<8192,256>>>();
    for(int it=0; it<3; it++){
        zero_stats<<<1,32>>>();
        conv3x3<<<dim3(3136,2),dim3(128,2)>>>(cw, cb);
        finalize_stats<<<1,32>>>();
        norm_gelu<<<dim3(1225,32),256>>>();
    }
    attn_kernel<<<8192,256>>>(mask, rpb);
    tgemm_nt<0><<<dim3(4,196),256>>>(p_ao, pw, pb, nullptr, p_proj, 512, 512);
    rev_ln2<<<TTOK,256>>>(x, n2w, n2b);
    tgemm_nt<1><<<dim3(16,196),256>>>(p_ln2, f1w, f1b, nullptr, p_fc1, 2048, 512);
    tgemm_nt<2><<<dim3(4,196),256>>>(p_fc1, f2w, f2b, p_x2, out, 512, 2048);
}